// round 1
// baseline (speedup 1.0000x reference)
#include <cuda_runtime.h>

#define NLAYER   16
#define DIM      64
#define NHID     256
#define TB       32
#define NTHREADS 256
#define KC       16
#define W0_SZ    (DIM*NHID)     // 16384
#define W1_SZ    (NHID*NHID)    // 65536
#define W2_SZ    (NHID*DIM)     // 16384
#define WNET     (W0_SZ+W1_SZ+W2_SZ)  // 98304
#define YS       (DIM+4)        // 68
#define HS       (NHID+4)       // 260

// smem: y[TB][YS] + h0[TB][HS] + h1[TB][HS] + Wbuf[2][KC*NHID]
#define SMEM_FLOATS (TB*YS + 2*TB*HS + 2*KC*NHID)
#define SMEM_BYTES  (SMEM_FLOATS*4)

__device__ __align__(16) float g_WT[2*NLAYER*WNET];

typedef unsigned long long ull;

static __device__ __forceinline__ ull pack2(float lo, float hi) {
    ull r; asm("mov.b64 %0, {%1,%2};" : "=l"(r) : "f"(lo), "f"(hi)); return r;
}
static __device__ __forceinline__ void unpack2(ull v, float& lo, float& hi) {
    asm("mov.b64 {%0,%1}, %2;" : "=f"(lo), "=f"(hi) : "l"(v));
}
static __device__ __forceinline__ void ffma2(ull& acc, ull a, ull b) {
    asm("fma.rn.f32x2 %0, %1, %2, %0;" : "+l"(acc) : "l"(a), "l"(b));
}
static __device__ __forceinline__ void cp16(float* sdst, const float* gsrc) {
    unsigned s = (unsigned)__cvta_generic_to_shared(sdst);
    asm volatile("cp.async.cg.shared.global [%0], [%1], 16;" :: "r"(s), "l"(gsrc) : "memory");
}
static __device__ __forceinline__ void cp_commit() {
    asm volatile("cp.async.commit_group;" ::: "memory");
}
static __device__ __forceinline__ void cp_wait0() {
    asm volatile("cp.async.wait_group 0;" ::: "memory");
}

// ---------------- precompute: masked + transposed weights --------------------
__global__ void mask_kernel(
    const float* __restrict__ lW0, const float* __restrict__ lW1, const float* __restrict__ lW2,
    const float* __restrict__ sW0, const float* __restrict__ sW1, const float* __restrict__ sW2,
    const float* __restrict__ M0,  const float* __restrict__ M1,  const float* __restrict__ M2)
{
    int idx = blockIdx.x * blockDim.x + threadIdx.x;
    const int total = 2 * NLAYER * WNET;
    if (idx >= total) return;
    int ln  = idx / WNET;     // (layer, net) pair
    int off = idx % WNET;
    int l   = ln >> 1;
    int net = ln & 1;
    float v;
    if (off < W0_SZ) {
        int k = off / NHID, n = off % NHID;                 // WT0[k<64][n<256]
        const float* W = net ? sW0 : lW0;
        int s = l*W0_SZ + n*DIM + k;
        v = W[s] * M0[s];
    } else if (off < W0_SZ + W1_SZ) {
        int o = off - W0_SZ; int k = o / NHID, n = o % NHID; // WT1[k<256][n<256]
        const float* W = net ? sW1 : lW1;
        int s = l*W1_SZ + n*NHID + k;
        v = W[s] * M1[s];
    } else {
        int o = off - W0_SZ - W1_SZ; int k = o / DIM, n = o % DIM; // WT2[k<256][n<64]
        const float* W = net ? sW2 : lW2;
        int s = l*W2_SZ + n*NHID + k;
        v = W[s] * M2[s];
    }
    g_WT[idx] = v;
}

// ---------------- fused stage: out[TB][N] = act(in[TB][K] @ WT + b) ----------
// MODE 0: relu -> outbuf (stride HS)
// MODE 1: keep raw result in locreg (loc net output)
// MODE 2: coupling: ybuf = exp(-res) * (ybuf - locreg)
template<int K, int N, int INSTRIDE, int MODE>
__device__ __forceinline__ void stage(
    const float* __restrict__ Wg, const float* __restrict__ bg,
    const float* __restrict__ in, float* __restrict__ outbuf,
    float* __restrict__ Wbuf, ull* locreg, float* __restrict__ ybuf,
    int tx, int ty, int tid)
{
    constexpr int NC     = N / 32;          // f32x2 column pairs per thread
    constexpr int R      = TB / 16;         // rows per thread (2)
    constexpr int NCHUNK = K / KC;          // even for all stages
    constexpr int F4     = KC * N / 4;      // float4 per chunk
    constexpr int LD     = F4 / NTHREADS;   // float4 per thread per chunk (>=1)
    constexpr int BUFSTRIDE = KC * N;

    ull acc[R][NC];
    #pragma unroll
    for (int j = 0; j < NC; j++) {
        ull bb = *(const ull*)(bg + 2*(tx + 16*j));
        #pragma unroll
        for (int i = 0; i < R; i++) acc[i][j] = bb;
    }

    // preload chunk 0 into buffer 0
    #pragma unroll
    for (int v = 0; v < LD; v++) {
        int f4 = tid + v * NTHREADS;
        cp16(Wbuf + f4*4, Wg + f4*4);
    }
    cp_commit();

    #pragma unroll 1
    for (int cc = 0; cc < NCHUNK; cc++) {
        cp_wait0();
        __syncthreads();
        if (cc + 1 < NCHUNK) {
            float* dst = Wbuf + ((cc + 1) & 1) * BUFSTRIDE;
            const float* src = Wg + (cc + 1) * KC * N;
            #pragma unroll
            for (int v = 0; v < LD; v++) {
                int f4 = tid + v * NTHREADS;
                cp16(dst + f4*4, src + f4*4);
            }
            cp_commit();
        }
        const float* wb = Wbuf + (cc & 1) * BUFSTRIDE;
        #pragma unroll
        for (int kk = 0; kk < KC; kk++) {
            ull a2[R];
            #pragma unroll
            for (int i = 0; i < R; i++) {
                float av = in[(ty*R + i) * INSTRIDE + cc*KC + kk];
                a2[i] = pack2(av, av);
            }
            #pragma unroll
            for (int j = 0; j < NC; j++) {
                ull w2 = *(const ull*)(wb + kk*N + 2*(tx + 16*j));
                #pragma unroll
                for (int i = 0; i < R; i++) ffma2(acc[i][j], a2[i], w2);
            }
        }
    }

    // epilogue
    #pragma unroll
    for (int i = 0; i < R; i++) {
        int row = ty*R + i;
        #pragma unroll
        for (int j = 0; j < NC; j++) {
            int c = 2*(tx + 16*j);
            if (MODE == 0) {
                float lo, hi; unpack2(acc[i][j], lo, hi);
                float2 v; v.x = fmaxf(lo, 0.f); v.y = fmaxf(hi, 0.f);
                *(float2*)(outbuf + row*HS + c) = v;
            } else if (MODE == 1) {
                locreg[i*NC + j] = acc[i][j];
            } else {
                float s0, s1, l0, l1;
                unpack2(acc[i][j], s0, s1);
                unpack2(locreg[i*NC + j], l0, l1);
                float* yp = ybuf + row*YS + c;
                float y0 = yp[0], y1 = yp[1];
                yp[0] = expf(-s0) * (y0 - l0);
                yp[1] = expf(-s1) * (y1 - l1);
            }
        }
    }
}

// ---------------- persistent flow kernel -------------------------------------
__global__ void __launch_bounds__(NTHREADS, 2) flow_kernel(
    const float* __restrict__ u,
    const float* __restrict__ lb0, const float* __restrict__ lb1, const float* __restrict__ lb2,
    const float* __restrict__ sb0, const float* __restrict__ sb1, const float* __restrict__ sb2,
    float* __restrict__ out)
{
    extern __shared__ float sm[];
    float* ybuf = sm;                      // TB*YS
    float* h0   = ybuf + TB*YS;            // TB*HS
    float* h1   = h0   + TB*HS;            // TB*HS
    float* Wbuf = h1   + TB*HS;            // 2*KC*NHID

    int tid = threadIdx.x;
    int tx = tid & 15, ty = tid >> 4;
    int row0 = blockIdx.x * TB;

    // load y tile (u)
    #pragma unroll
    for (int v = tid; v < TB*DIM/4; v += NTHREADS) {
        int row = v / (DIM/4), k4 = v % (DIM/4);
        float4 t = *(const float4*)(u + (size_t)(row0 + row)*DIM + k4*4);
        *(float4*)(ybuf + row*YS + k4*4) = t;
    }

    ull locreg[2 * (DIM/32)];  // R * NC_C = 2*2

    #pragma unroll 1
    for (int l = 0; l < NLAYER; l++) {
        #pragma unroll 1
        for (int net = 0; net < 2; net++) {
            const float* W  = g_WT + (size_t)(2*l + net) * WNET;
            const float* b0 = (net ? sb0 : lb0) + l*NHID;
            const float* b1 = (net ? sb1 : lb1) + l*NHID;
            const float* b2 = (net ? sb2 : lb2) + l*DIM;

            stage<DIM,  NHID, YS, 0>(W,                 b0, ybuf, h0,   Wbuf, nullptr, nullptr, tx, ty, tid);
            stage<NHID, NHID, HS, 0>(W + W0_SZ,         b1, h0,   h1,   Wbuf, nullptr, nullptr, tx, ty, tid);
            if (net == 0)
                stage<NHID, DIM, HS, 1>(W + W0_SZ + W1_SZ, b2, h1, nullptr, Wbuf, locreg, nullptr, tx, ty, tid);
            else
                stage<NHID, DIM, HS, 2>(W + W0_SZ + W1_SZ, b2, h1, nullptr, Wbuf, locreg, ybuf,   tx, ty, tid);
        }
    }

    __syncthreads();
    #pragma unroll
    for (int v = tid; v < TB*DIM/4; v += NTHREADS) {
        int row = v / (DIM/4), k4 = v % (DIM/4);
        *(float4*)(out + (size_t)(row0 + row)*DIM + k4*4) =
            *(const float4*)(ybuf + row*YS + k4*4);
    }
}

// ---------------- launch ------------------------------------------------------
extern "C" void kernel_launch(void* const* d_in, const int* in_sizes, int n_in,
                              void* d_out, int out_size)
{
    const float* u   = (const float*)d_in[0];
    const float* lW0 = (const float*)d_in[1];
    const float* lb0 = (const float*)d_in[2];
    const float* lW1 = (const float*)d_in[3];
    const float* lb1 = (const float*)d_in[4];
    const float* lW2 = (const float*)d_in[5];
    const float* lb2 = (const float*)d_in[6];
    const float* sW0 = (const float*)d_in[7];
    const float* sb0 = (const float*)d_in[8];
    const float* sW1 = (const float*)d_in[9];
    const float* sb1 = (const float*)d_in[10];
    const float* sW2 = (const float*)d_in[11];
    const float* sb2 = (const float*)d_in[12];
    const float* M0  = (const float*)d_in[13];
    const float* M1  = (const float*)d_in[14];
    const float* M2  = (const float*)d_in[15];

    int rows = in_sizes[0] / DIM;

    cudaFuncSetAttribute(flow_kernel, cudaFuncAttributeMaxDynamicSharedMemorySize, SMEM_BYTES);

    const int total = 2 * NLAYER * WNET;
    mask_kernel<<<(total + 255) / 256, 256>>>(lW0, lW1, lW2, sW0, sW1, sW2, M0, M1, M2);

    flow_kernel<<<rows / TB, NTHREADS, SMEM_BYTES>>>(
        u, lb0, lb1, lb2, sb0, sb1, sb2, (float*)d_out);
}

// round 2
// speedup vs baseline: 1.4688x; 1.4688x over previous
#include <cuda_runtime.h>

#define NLAYER   16
#define DIM      64
#define NHID     256
#define TB       32
#define NTHREADS 128
#define KC       16
#define W0_SZ    (DIM*NHID)     // 16384
#define W1_SZ    (NHID*NHID)    // 65536
#define W2_SZ    (NHID*DIM)     // 16384
#define WNET     (W0_SZ+W1_SZ+W2_SZ)  // 98304
#define YS       (DIM+4)        // 68
#define HS       (NHID+4)       // 260

// smem: y[TB][YS] + h0[TB][HS] + h1[TB][HS] + Wbuf[2][KC*NHID]
#define SMEM_FLOATS (TB*YS + 2*TB*HS + 2*KC*NHID)
#define SMEM_BYTES  (SMEM_FLOATS*4)

__device__ __align__(16) float g_WT[2*NLAYER*WNET];

typedef unsigned long long ull;

static __device__ __forceinline__ ull pack2(float lo, float hi) {
    ull r; asm("mov.b64 %0, {%1,%2};" : "=l"(r) : "f"(lo), "f"(hi)); return r;
}
static __device__ __forceinline__ void unpack2(ull v, float& lo, float& hi) {
    asm("mov.b64 {%0,%1}, %2;" : "=f"(lo), "=f"(hi) : "l"(v));
}
static __device__ __forceinline__ void ffma2(ull& acc, ull a, ull b) {
    asm("fma.rn.f32x2 %0, %1, %2, %0;" : "+l"(acc) : "l"(a), "l"(b));
}
static __device__ __forceinline__ void cp16(float* sdst, const float* gsrc) {
    unsigned s = (unsigned)__cvta_generic_to_shared(sdst);
    asm volatile("cp.async.cg.shared.global [%0], [%1], 16;" :: "r"(s), "l"(gsrc) : "memory");
}
static __device__ __forceinline__ void cp_commit() {
    asm volatile("cp.async.commit_group;" ::: "memory");
}
static __device__ __forceinline__ void cp_wait0() {
    asm volatile("cp.async.wait_group 0;" ::: "memory");
}

// ---------------- precompute: masked + transposed weights --------------------
__global__ void mask_kernel(
    const float* __restrict__ lW0, const float* __restrict__ lW1, const float* __restrict__ lW2,
    const float* __restrict__ sW0, const float* __restrict__ sW1, const float* __restrict__ sW2,
    const float* __restrict__ M0,  const float* __restrict__ M1,  const float* __restrict__ M2)
{
    int idx = blockIdx.x * blockDim.x + threadIdx.x;
    const int total = 2 * NLAYER * WNET;
    if (idx >= total) return;
    int ln  = idx / WNET;     // (layer, net) pair
    int off = idx % WNET;
    int l   = ln >> 1;
    int net = ln & 1;
    float v;
    if (off < W0_SZ) {
        int k = off / NHID, n = off % NHID;                 // WT0[k<64][n<256]
        const float* W = net ? sW0 : lW0;
        int s = l*W0_SZ + n*DIM + k;
        v = W[s] * M0[s];
    } else if (off < W0_SZ + W1_SZ) {
        int o = off - W0_SZ; int k = o / NHID, n = o % NHID; // WT1[k<256][n<256]
        const float* W = net ? sW1 : lW1;
        int s = l*W1_SZ + n*NHID + k;
        v = W[s] * M1[s];
    } else {
        int o = off - W0_SZ - W1_SZ; int k = o / DIM, n = o % DIM; // WT2[k<256][n<64]
        const float* W = net ? sW2 : lW2;
        int s = l*W2_SZ + n*NHID + k;
        v = W[s] * M2[s];
    }
    g_WT[idx] = v;
}

// ---------------- fused stage: out[TB][N] = act(in[TB][K] @ WT + b) ----------
// Thread layout: tx in [0,16) covers columns (f32x2 pairs, NC per thread),
//                ty in [0,8)  covers rows, R = TB/8 = 4 rows per thread.
// MODE 0: relu -> outbuf (stride HS)
// MODE 1: keep raw result in locreg (loc net output)
// MODE 2: coupling: ybuf = exp(-res) * (ybuf - locreg)
template<int K, int N, int INSTRIDE, int MODE>
__device__ __forceinline__ void stage(
    const float* __restrict__ Wg, const float* __restrict__ bg,
    const float* __restrict__ in, float* __restrict__ outbuf,
    float* __restrict__ Wbuf, ull* locreg, float* __restrict__ ybuf,
    int tx, int ty, int tid)
{
    constexpr int NC     = N / 32;          // f32x2 column pairs per thread
    constexpr int R      = 4;               // rows per thread
    constexpr int NCHUNK = K / KC;
    constexpr int F4     = KC * N / 4;      // float4 per chunk
    constexpr int LD     = F4 / NTHREADS;   // float4 per thread per chunk
    constexpr int BUFSTRIDE = KC * N;

    ull acc[R][NC];
    #pragma unroll
    for (int j = 0; j < NC; j++) {
        ull bb = *(const ull*)(bg + 2*(tx + 16*j));
        #pragma unroll
        for (int i = 0; i < R; i++) acc[i][j] = bb;
    }

    // preload chunk 0 into buffer 0
    #pragma unroll
    for (int v = 0; v < LD; v++) {
        int f4 = tid + v * NTHREADS;
        cp16(Wbuf + f4*4, Wg + f4*4);
    }
    cp_commit();

    #pragma unroll 1
    for (int cc = 0; cc < NCHUNK; cc++) {
        cp_wait0();
        __syncthreads();
        if (cc + 1 < NCHUNK) {
            float* dst = Wbuf + ((cc + 1) & 1) * BUFSTRIDE;
            const float* src = Wg + (cc + 1) * KC * N;
            #pragma unroll
            for (int v = 0; v < LD; v++) {
                int f4 = tid + v * NTHREADS;
                cp16(dst + f4*4, src + f4*4);
            }
            cp_commit();
        }
        const float* wb = Wbuf + (cc & 1) * BUFSTRIDE;
        #pragma unroll
        for (int k4 = 0; k4 < KC/4; k4++) {
            // vectorized activation load: 4 k-values per row
            float4 a4[R];
            #pragma unroll
            for (int i = 0; i < R; i++)
                a4[i] = *(const float4*)(in + (ty*R + i) * INSTRIDE + cc*KC + k4*4);
            #pragma unroll
            for (int q = 0; q < 4; q++) {
                ull a2[R];
                #pragma unroll
                for (int i = 0; i < R; i++) {
                    float av = ((const float*)&a4[i])[q];
                    a2[i] = pack2(av, av);
                }
                int kk = k4*4 + q;
                #pragma unroll
                for (int j = 0; j < NC; j++) {
                    ull w2 = *(const ull*)(wb + kk*N + 2*(tx + 16*j));
                    #pragma unroll
                    for (int i = 0; i < R; i++) ffma2(acc[i][j], a2[i], w2);
                }
            }
        }
    }

    // epilogue
    #pragma unroll
    for (int i = 0; i < R; i++) {
        int row = ty*R + i;
        #pragma unroll
        for (int j = 0; j < NC; j++) {
            int c = 2*(tx + 16*j);
            if (MODE == 0) {
                float lo, hi; unpack2(acc[i][j], lo, hi);
                float2 v; v.x = fmaxf(lo, 0.f); v.y = fmaxf(hi, 0.f);
                *(float2*)(outbuf + row*HS + c) = v;
            } else if (MODE == 1) {
                locreg[i*NC + j] = acc[i][j];
            } else {
                float s0, s1, l0, l1;
                unpack2(acc[i][j], s0, s1);
                unpack2(locreg[i*NC + j], l0, l1);
                float* yp = ybuf + row*YS + c;
                float y0 = yp[0], y1 = yp[1];
                yp[0] = expf(-s0) * (y0 - l0);
                yp[1] = expf(-s1) * (y1 - l1);
            }
        }
    }
}

// ---------------- persistent flow kernel -------------------------------------
__global__ void __launch_bounds__(NTHREADS, 2) flow_kernel(
    const float* __restrict__ u,
    const float* __restrict__ lb0, const float* __restrict__ lb1, const float* __restrict__ lb2,
    const float* __restrict__ sb0, const float* __restrict__ sb1, const float* __restrict__ sb2,
    float* __restrict__ out)
{
    extern __shared__ float sm[];
    float* ybuf = sm;                      // TB*YS
    float* h0   = ybuf + TB*YS;            // TB*HS
    float* h1   = h0   + TB*HS;            // TB*HS
    float* Wbuf = h1   + TB*HS;            // 2*KC*NHID

    int tid = threadIdx.x;
    int tx = tid & 15, ty = tid >> 4;
    int row0 = blockIdx.x * TB;

    // load y tile (u)
    #pragma unroll
    for (int v = tid; v < TB*DIM/4; v += NTHREADS) {
        int row = v / (DIM/4), k4 = v % (DIM/4);
        float4 t = *(const float4*)(u + (size_t)(row0 + row)*DIM + k4*4);
        *(float4*)(ybuf + row*YS + k4*4) = t;
    }

    ull locreg[4 * (DIM/32)];  // R * NC_C = 4*2

    #pragma unroll 1
    for (int l = 0; l < NLAYER; l++) {
        #pragma unroll 1
        for (int net = 0; net < 2; net++) {
            const float* W  = g_WT + (size_t)(2*l + net) * WNET;
            const float* b0 = (net ? sb0 : lb0) + l*NHID;
            const float* b1 = (net ? sb1 : lb1) + l*NHID;
            const float* b2 = (net ? sb2 : lb2) + l*DIM;

            stage<DIM,  NHID, YS, 0>(W,                 b0, ybuf, h0,   Wbuf, nullptr, nullptr, tx, ty, tid);
            stage<NHID, NHID, HS, 0>(W + W0_SZ,         b1, h0,   h1,   Wbuf, nullptr, nullptr, tx, ty, tid);
            if (net == 0)
                stage<NHID, DIM, HS, 1>(W + W0_SZ + W1_SZ, b2, h1, nullptr, Wbuf, locreg, nullptr, tx, ty, tid);
            else
                stage<NHID, DIM, HS, 2>(W + W0_SZ + W1_SZ, b2, h1, nullptr, Wbuf, locreg, ybuf,   tx, ty, tid);
        }
    }

    __syncthreads();
    #pragma unroll
    for (int v = tid; v < TB*DIM/4; v += NTHREADS) {
        int row = v / (DIM/4), k4 = v % (DIM/4);
        *(float4*)(out + (size_t)(row0 + row)*DIM + k4*4) =
            *(const float4*)(ybuf + row*YS + k4*4);
    }
}

// ---------------- launch ------------------------------------------------------
extern "C" void kernel_launch(void* const* d_in, const int* in_sizes, int n_in,
                              void* d_out, int out_size)
{
    const float* u   = (const float*)d_in[0];
    const float* lW0 = (const float*)d_in[1];
    const float* lb0 = (const float*)d_in[2];
    const float* lW1 = (const float*)d_in[3];
    const float* lb1 = (const float*)d_in[4];
    const float* lW2 = (const float*)d_in[5];
    const float* lb2 = (const float*)d_in[6];
    const float* sW0 = (const float*)d_in[7];
    const float* sb0 = (const float*)d_in[8];
    const float* sW1 = (const float*)d_in[9];
    const float* sb1 = (const float*)d_in[10];
    const float* sW2 = (const float*)d_in[11];
    const float* sb2 = (const float*)d_in[12];
    const float* M0  = (const float*)d_in[13];
    const float* M1  = (const float*)d_in[14];
    const float* M2  = (const float*)d_in[15];

    int rows = in_sizes[0] / DIM;

    cudaFuncSetAttribute(flow_kernel, cudaFuncAttributeMaxDynamicSharedMemorySize, SMEM_BYTES);

    const int total = 2 * NLAYER * WNET;
    mask_kernel<<<(total + 255) / 256, 256>>>(lW0, lW1, lW2, sW0, sW1, sW2, M0, M1, M2);

    flow_kernel<<<rows / TB, NTHREADS, SMEM_BYTES>>>(
        u, lb0, lb1, lb2, sb0, sb1, sb2, (float*)d_out);
}

// round 3
// speedup vs baseline: 1.5520x; 1.0567x over previous
#include <cuda_runtime.h>

#define NLAYER   16
#define DIM      64
#define NHID     256
#define TB       32
#define NTHREADS 128
#define KC       16
#define W0_SZ    (DIM*NHID)     // 16384
#define W1_SZ    (NHID*NHID)    // 65536
#define W2_SZ    (NHID*DIM)     // 16384
#define WNET     (W0_SZ+W1_SZ+W2_SZ)  // 98304
#define YS       (DIM+4)        // 68
#define HS       (NHID+4)       // 260

// smem: y[TB][YS] + h0[TB][HS] + h1[TB][HS] + Wbuf[2][KC*NHID]
#define SMEM_FLOATS (TB*YS + 2*TB*HS + 2*KC*NHID)
#define SMEM_BYTES  (SMEM_FLOATS*4)

__device__ __align__(16) float g_WT[2*NLAYER*WNET];

typedef unsigned long long ull;

static __device__ __forceinline__ ull pack2(float lo, float hi) {
    ull r; asm("mov.b64 %0, {%1,%2};" : "=l"(r) : "f"(lo), "f"(hi)); return r;
}
static __device__ __forceinline__ void unpack2(ull v, float& lo, float& hi) {
    asm("mov.b64 {%0,%1}, %2;" : "=f"(lo), "=f"(hi) : "l"(v));
}
static __device__ __forceinline__ void ffma2(ull& acc, ull a, ull b) {
    asm("fma.rn.f32x2 %0, %1, %2, %0;" : "+l"(acc) : "l"(a), "l"(b));
}
static __device__ __forceinline__ void cp16(float* sdst, const float* gsrc) {
    unsigned s = (unsigned)__cvta_generic_to_shared(sdst);
    asm volatile("cp.async.cg.shared.global [%0], [%1], 16;" :: "r"(s), "l"(gsrc) : "memory");
}
static __device__ __forceinline__ void cp_commit() {
    asm volatile("cp.async.commit_group;" ::: "memory");
}
static __device__ __forceinline__ void cp_wait0() {
    asm volatile("cp.async.wait_group 0;" ::: "memory");
}

// ---------------- precompute: masked + transposed weights --------------------
__global__ void mask_kernel(
    const float* __restrict__ lW0, const float* __restrict__ lW1, const float* __restrict__ lW2,
    const float* __restrict__ sW0, const float* __restrict__ sW1, const float* __restrict__ sW2,
    const float* __restrict__ M0,  const float* __restrict__ M1,  const float* __restrict__ M2)
{
    int idx = blockIdx.x * blockDim.x + threadIdx.x;
    const int total = 2 * NLAYER * WNET;
    if (idx >= total) return;
    int ln  = idx / WNET;     // (layer, net) pair
    int off = idx % WNET;
    int l   = ln >> 1;
    int net = ln & 1;
    float v;
    if (off < W0_SZ) {
        int k = off / NHID, n = off % NHID;                 // WT0[k<64][n<256]
        const float* W = net ? sW0 : lW0;
        int s = l*W0_SZ + n*DIM + k;
        v = W[s] * M0[s];
    } else if (off < W0_SZ + W1_SZ) {
        int o = off - W0_SZ; int k = o / NHID, n = o % NHID; // WT1[k<256][n<256]
        const float* W = net ? sW1 : lW1;
        int s = l*W1_SZ + n*NHID + k;
        v = W[s] * M1[s];
    } else {
        int o = off - W0_SZ - W1_SZ; int k = o / DIM, n = o % DIM; // WT2[k<256][n<64]
        const float* W = net ? sW2 : lW2;
        int s = l*W2_SZ + n*NHID + k;
        v = W[s] * M2[s];
    }
    g_WT[idx] = v;
}

// ---------------- fused stage: out[TB][N] = act(in[TB][K] @ WT + b) ----------
// Thread layout: tx in [0,16) covers columns (f32x2 pairs, NC per thread),
//                ty in [0,8)  covers rows, R = TB/8 = 4 rows per thread.
// MODE 0: relu -> outbuf (stride HS)
// MODE 1: keep raw result in locreg (loc net output)
// MODE 2: coupling: ybuf = exp(-res) * (ybuf - locreg)
template<int K, int N, int INSTRIDE, int MODE>
__device__ __forceinline__ void stage(
    const float* __restrict__ Wg, const float* __restrict__ bg,
    const float* __restrict__ in, float* __restrict__ outbuf,
    float* __restrict__ Wbuf, ull* locreg, float* __restrict__ ybuf,
    int tx, int ty, int tid)
{
    constexpr int NC     = N / 32;          // f32x2 column pairs per thread
    constexpr int R      = 4;               // rows per thread
    constexpr int NCHUNK = K / KC;
    constexpr int F4     = KC * N / 4;      // float4 per chunk
    constexpr int LD     = F4 / NTHREADS;   // float4 per thread per chunk
    constexpr int BUFSTRIDE = KC * N;

    ull acc[R][NC];
    #pragma unroll
    for (int j = 0; j < NC; j++) {
        ull bb = *(const ull*)(bg + 2*(tx + 16*j));
        #pragma unroll
        for (int i = 0; i < R; i++) acc[i][j] = bb;
    }

    // preload chunk 0 into buffer 0
    #pragma unroll
    for (int v = 0; v < LD; v++) {
        int f4 = tid + v * NTHREADS;
        cp16(Wbuf + f4*4, Wg + f4*4);
    }
    cp_commit();

    #pragma unroll 1
    for (int cc = 0; cc < NCHUNK; cc++) {
        cp_wait0();
        __syncthreads();
        if (cc + 1 < NCHUNK) {
            float* dst = Wbuf + ((cc + 1) & 1) * BUFSTRIDE;
            const float* src = Wg + (cc + 1) * KC * N;
            #pragma unroll
            for (int v = 0; v < LD; v++) {
                int f4 = tid + v * NTHREADS;
                cp16(dst + f4*4, src + f4*4);
            }
            cp_commit();
        }
        const float* wb = Wbuf + (cc & 1) * BUFSTRIDE;
        #pragma unroll
        for (int k4 = 0; k4 < KC/4; k4++) {
            // vectorized activation load: 4 k-values per row
            float4 a4[R];
            #pragma unroll
            for (int i = 0; i < R; i++)
                a4[i] = *(const float4*)(in + (ty*R + i) * INSTRIDE + cc*KC + k4*4);
            #pragma unroll
            for (int q = 0; q < 4; q++) {
                ull a2[R];
                #pragma unroll
                for (int i = 0; i < R; i++) {
                    float av = ((const float*)&a4[i])[q];
                    a2[i] = pack2(av, av);
                }
                int kk = k4*4 + q;
                #pragma unroll
                for (int j = 0; j < NC; j++) {
                    ull w2 = *(const ull*)(wb + kk*N + 2*(tx + 16*j));
                    #pragma unroll
                    for (int i = 0; i < R; i++) ffma2(acc[i][j], a2[i], w2);
                }
            }
        }
    }

    // epilogue
    #pragma unroll
    for (int i = 0; i < R; i++) {
        int row = ty*R + i;
        #pragma unroll
        for (int j = 0; j < NC; j++) {
            int c = 2*(tx + 16*j);
            if (MODE == 0) {
                float lo, hi; unpack2(acc[i][j], lo, hi);
                float2 v; v.x = fmaxf(lo, 0.f); v.y = fmaxf(hi, 0.f);
                *(float2*)(outbuf + row*HS + c) = v;
            } else if (MODE == 1) {
                locreg[i*NC + j] = acc[i][j];
            } else {
                float s0, s1, l0, l1;
                unpack2(acc[i][j], s0, s1);
                unpack2(locreg[i*NC + j], l0, l1);
                float* yp = ybuf + row*YS + c;
                float y0 = yp[0], y1 = yp[1];
                yp[0] = expf(-s0) * (y0 - l0);
                yp[1] = expf(-s1) * (y1 - l1);
            }
        }
    }
}

// ---------------- persistent flow kernel -------------------------------------
__global__ void __launch_bounds__(NTHREADS, 2) flow_kernel(
    const float* __restrict__ u,
    const float* __restrict__ lb0, const float* __restrict__ lb1, const float* __restrict__ lb2,
    const float* __restrict__ sb0, const float* __restrict__ sb1, const float* __restrict__ sb2,
    float* __restrict__ out)
{
    extern __shared__ float sm[];
    float* ybuf = sm;                      // TB*YS
    float* h0   = ybuf + TB*YS;            // TB*HS
    float* h1   = h0   + TB*HS;            // TB*HS
    float* Wbuf = h1   + TB*HS;            // 2*KC*NHID

    int tid = threadIdx.x;
    int tx = tid & 15, ty = tid >> 4;
    int row0 = blockIdx.x * TB;

    // load y tile (u)
    #pragma unroll
    for (int v = tid; v < TB*DIM/4; v += NTHREADS) {
        int row = v / (DIM/4), k4 = v % (DIM/4);
        float4 t = *(const float4*)(u + (size_t)(row0 + row)*DIM + k4*4);
        *(float4*)(ybuf + row*YS + k4*4) = t;
    }

    ull locreg[4 * (DIM/32)];  // R * NC_C = 4*2

    #pragma unroll 1
    for (int l = 0; l < NLAYER; l++) {
        #pragma unroll 1
        for (int net = 0; net < 2; net++) {
            const float* W  = g_WT + (size_t)(2*l + net) * WNET;
            const float* b0 = (net ? sb0 : lb0) + l*NHID;
            const float* b1 = (net ? sb1 : lb1) + l*NHID;
            const float* b2 = (net ? sb2 : lb2) + l*DIM;

            stage<DIM,  NHID, YS, 0>(W,                 b0, ybuf, h0,   Wbuf, nullptr, nullptr, tx, ty, tid);
            stage<NHID, NHID, HS, 0>(W + W0_SZ,         b1, h0,   h1,   Wbuf, nullptr, nullptr, tx, ty, tid);
            if (net == 0)
                stage<NHID, DIM, HS, 1>(W + W0_SZ + W1_SZ, b2, h1, nullptr, Wbuf, locreg, nullptr, tx, ty, tid);
            else
                stage<NHID, DIM, HS, 2>(W + W0_SZ + W1_SZ, b2, h1, nullptr, Wbuf, locreg, ybuf,   tx, ty, tid);
        }
    }

    __syncthreads();
    #pragma unroll
    for (int v = tid; v < TB*DIM/4; v += NTHREADS) {
        int row = v / (DIM/4), k4 = v % (DIM/4);
        *(float4*)(out + (size_t)(row0 + row)*DIM + k4*4) =
            *(const float4*)(ybuf + row*YS + k4*4);
    }
}

// ---------------- launch ------------------------------------------------------
extern "C" void kernel_launch(void* const* d_in, const int* in_sizes, int n_in,
                              void* d_out, int out_size)
{
    const float* u   = (const float*)d_in[0];
    const float* lW0 = (const float*)d_in[1];
    const float* lb0 = (const float*)d_in[2];
    const float* lW1 = (const float*)d_in[3];
    const float* lb1 = (const float*)d_in[4];
    const float* lW2 = (const float*)d_in[5];
    const float* lb2 = (const float*)d_in[6];
    const float* sW0 = (const float*)d_in[7];
    const float* sb0 = (const float*)d_in[8];
    const float* sW1 = (const float*)d_in[9];
    const float* sb1 = (const float*)d_in[10];
    const float* sW2 = (const float*)d_in[11];
    const float* sb2 = (const float*)d_in[12];
    const float* M0  = (const float*)d_in[13];
    const float* M1  = (const float*)d_in[14];
    const float* M2  = (const float*)d_in[15];

    int rows = in_sizes[0] / DIM;

    cudaFuncSetAttribute(flow_kernel, cudaFuncAttributeMaxDynamicSharedMemorySize, SMEM_BYTES);

    const int total = 2 * NLAYER * WNET;
    mask_kernel<<<(total + 255) / 256, 256>>>(lW0, lW1, lW2, sW0, sW1, sW2, M0, M1, M2);

    flow_kernel<<<rows / TB, NTHREADS, SMEM_BYTES>>>(
        u, lb0, lb1, lb2, sb0, sb1, sb2, (float*)d_out);
}

// round 5
// speedup vs baseline: 2.9276x; 1.8863x over previous
#include <cuda_runtime.h>
#include <cuda_bf16.h>

typedef unsigned int u32;

#define DIM 64
#define NHID 256
#define W0_SZ (DIM*NHID)
#define W1_SZ (NHID*NHID)
#define W2_SZ (NHID*DIM)
#define WNET  (W0_SZ+W1_SZ+W2_SZ)

#define TBR 128
#define NTHREADS 512
#define CH_BIG 24576
#define CH_SM  6144
#define PAIR_BYTES (20*CH_BIG + 16*CH_SM)   /* 589824 */
#define NCH (32*36)

#define SM_W   0u
#define SM_AHI 49152u
#define SM_ALO 114688u
#define SM_LOC 180224u
#define SM_TOTAL 214016u

__device__ __align__(16) unsigned char g_W[(size_t)32*PAIR_BYTES];

static __device__ __forceinline__ u32 s2u(const void* p){
  u32 a; asm("{ .reg .u64 t; cvta.to.shared.u64 t, %1; cvt.u32.u64 %0, t; }":"=r"(a):"l"(p)); return a;
}
static __device__ __forceinline__ void cp16(u32 sdst, const void* g){
  asm volatile("cp.async.cg.shared.global [%0], [%1], 16;"::"r"(sdst),"l"(g):"memory");
}
static __device__ __forceinline__ void ldsm4(u32* r, u32 a){
  asm volatile("ldmatrix.sync.aligned.m8n8.x4.shared.b16 {%0,%1,%2,%3}, [%4];"
    :"=r"(r[0]),"=r"(r[1]),"=r"(r[2]),"=r"(r[3]):"r"(a));
}
static __device__ __forceinline__ void mma_bf16(float* d, const u32* a, const u32* b){
  asm volatile("mma.sync.aligned.m16n8k16.row.col.f32.bf16.bf16.f32 "
    "{%0,%1,%2,%3}, {%4,%5,%6,%7}, {%8,%9}, {%0,%1,%2,%3};"
    :"+f"(d[0]),"+f"(d[1]),"+f"(d[2]),"+f"(d[3])
    :"r"(a[0]),"r"(a[1]),"r"(a[2]),"r"(a[3]),"r"(b[0]),"r"(b[1]));
}
static __device__ __forceinline__ u32 packbf(float lo, float hi){
  u32 r; asm("cvt.rn.bf16x2.f32 %0, %1, %2;":"=r"(r):"f"(hi),"f"(lo)); return r;
}
// write 2 consecutive cols (c,c+1) of one row into A hi/lo swizzled tiles
static __device__ __forceinline__ void writeA2(unsigned char* smp, int row, int c, float v0, float v1){
  u32 unit = (u32)c >> 3;
  u32 off = (u32)row*512u + (((unit ^ ((u32)row & 7u)) << 4) | (((u32)c & 7u) << 1));
  u32 h = packbf(v0, v1);
  float h0 = __uint_as_float(h << 16);
  float h1 = __uint_as_float(h & 0xFFFF0000u);
  u32 lo = packbf(v0 - h0, v1 - h1);
  *(u32*)(smp + SM_AHI + off) = h;
  *(u32*)(smp + SM_ALO + off) = lo;
}

static __device__ __forceinline__ void prefetch(u32 smb, int c, int tid){
  if (c < NCH){
    int pr = c/36, ci = c - pr*36;
    size_t off = (size_t)pr*PAIR_BYTES +
        (ci < 20 ? (size_t)ci*CH_BIG : (size_t)20*CH_BIG + (size_t)(ci-20)*CH_SM);
    int bytes = ci < 20 ? CH_BIG : CH_SM;
    const unsigned char* src = g_W + off;
    u32 dst = smb + SM_W + (u32)(c & 1)*CH_BIG;
    for (int o = tid*16; o < bytes; o += NTHREADS*16)
      cp16(dst + o, src + o);
  }
  asm volatile("cp.async.commit_group;":::"memory");
}

// one K=16 chunk: 12 ldmatrix + 48 (or 12) mma per warp
template<int NW, int LOFF>
static __device__ __forceinline__ void do_chunk(float (*acc)[4], u32 smb, unsigned char* smp,
                                                int slot, int ku0, int wm, int wn, int lane)
{
  (void)smp;
  int q = lane >> 3, ln = lane & 7;
  u32 ah[2][4], al[2][4];
  u32 arow0 = (u32)(wm*32 + ((q & 1) << 3) + ln);
  u32 aunit = (u32)(ku0 + (q >> 1));
  #pragma unroll
  for (int i = 0; i < 2; i++){
    u32 r = arow0 + (u32)i*16u;
    u32 aoff = r*512u + ((aunit ^ (r & 7u)) << 4);
    ldsm4(ah[i], smb + SM_AHI + aoff);
    ldsm4(al[i], smb + SM_ALO + aoff);
  }
  u32 wb = smb + SM_W + (u32)slot*CH_BIG;
  #pragma unroll
  for (int g = 0; g < NW/16; g++){
    u32 n = (u32)(wn*NW + g*16 + ((q >> 1) << 3) + ln);
    u32 boff = n*48u + (u32)((q & 1) << 4);
    u32 bh[4], bl[4];
    ldsm4(bh, wb + boff);
    ldsm4(bl, wb + LOFF + boff);
    #pragma unroll
    for (int i = 0; i < 2; i++){
      #pragma unroll
      for (int tt = 0; tt < 2; tt++){
        float* d = acc[i*8 + g*2 + tt];
        mma_bf16(d, ah[i], bh + tt*2);
        mma_bf16(d, al[i], bh + tt*2);
        mma_bf16(d, ah[i], bl + tt*2);
      }
    }
  }
}

template<int KCH, int NW, int LOFF>
static __device__ __forceinline__ void run_stage(float (*acc)[4], u32 smb, unsigned char* smp,
                                                 int& gc, int wm, int wn, int lane, int tid)
{
  #pragma unroll
  for (int t = 0; t < 16; t++){ acc[t][0]=0.f; acc[t][1]=0.f; acc[t][2]=0.f; acc[t][3]=0.f; }
  #pragma unroll 1
  for (int kc = 0; kc < KCH; kc++){
    asm volatile("cp.async.wait_group 1;":::"memory");
    __syncthreads();
    do_chunk<NW,LOFF>(acc, smb, smp, gc & 1, kc*2, wm, wn, lane);
    __syncthreads();
    prefetch(smb, gc + 2, tid);
    gc++;
  }
}

// ---------- prep: mask, bf16 hi/lo split, ldmatrix-ready slab image ----------
__global__ void prep_kernel(
    const float* __restrict__ lW0, const float* __restrict__ lW1, const float* __restrict__ lW2,
    const float* __restrict__ sW0, const float* __restrict__ sW1, const float* __restrict__ sW2,
    const float* __restrict__ M0,  const float* __restrict__ M1,  const float* __restrict__ M2)
{
    int idx = blockIdx.x*blockDim.x + threadIdx.x;
    if (idx >= 32*WNET) return;
    int pair = idx / WNET, off = idx % WNET;
    int l = pair >> 1, net = pair & 1;
    float w; size_t dst; int loff;
    size_t base = (size_t)pair*PAIR_BYTES;
    if (off < W0_SZ){
        int n = off >> 6, k = off & 63;
        int s = l*W0_SZ + off;
        w = (net ? sW0[s] : lW0[s]) * M0[s];
        dst = base + (size_t)(k >> 4)*CH_BIG + (size_t)n*48 + (size_t)(k & 15)*2;
        loff = 12288;
    } else if (off < W0_SZ + W1_SZ){
        int o = off - W0_SZ;
        int n = o >> 8, k = o & 255;
        int s = l*W1_SZ + o;
        w = (net ? sW1[s] : lW1[s]) * M1[s];
        dst = base + (size_t)(4 + (k >> 4))*CH_BIG + (size_t)n*48 + (size_t)(k & 15)*2;
        loff = 12288;
    } else {
        int o = off - W0_SZ - W1_SZ;
        int n = o >> 8, k = o & 255;
        int s = l*W2_SZ + o;
        w = (net ? sW2[s] : lW2[s]) * M2[s];
        dst = base + (size_t)20*CH_BIG + (size_t)(k >> 4)*CH_SM + (size_t)n*48 + (size_t)(k & 15)*2;
        loff = 3072;
    }
    __nv_bfloat16 hv = __float2bfloat16_rn(w);
    __nv_bfloat16 lv = __float2bfloat16_rn(w - __bfloat162float(hv));
    *(__nv_bfloat16*)(g_W + dst) = hv;
    *(__nv_bfloat16*)(g_W + dst + loff) = lv;
}

// ---------------- fused flow kernel ------------------------------------------
__global__ void __launch_bounds__(NTHREADS,1) flow_kernel(
    const float* __restrict__ u,
    const float* __restrict__ lb0, const float* __restrict__ lb1, const float* __restrict__ lb2,
    const float* __restrict__ sb0, const float* __restrict__ sb1, const float* __restrict__ sb2,
    float* __restrict__ out)
{
    extern __shared__ unsigned char smp[];
    u32 smb = s2u(smp);
    int tid = threadIdx.x, lane = tid & 31, wid = tid >> 5;
    int wm = wid >> 2, wn = wid & 3;
    int row0 = blockIdx.x * TBR;
    float* loc_sm = (float*)(smp + SM_LOC);

    int r0  = wm*32 + (lane >> 2);
    int cb  = wn*64 + (lane & 3)*2;   // stage0/1 col base (N=256)
    int cb2 = wn*16 + (lane & 3)*2;   // stage2 col base (N=64)

    float yv[16];
    #pragma unroll
    for (int i = 0; i < 2; i++)
      #pragma unroll
      for (int j = 0; j < 2; j++)
        #pragma unroll
        for (int rr = 0; rr < 2; rr++){
          int row = r0 + i*16 + rr*8;
          int c = cb2 + j*8;
          float2 v = *(const float2*)(u + (size_t)(row0 + row)*DIM + c);
          yv[i*8 + j*4 + rr*2]     = v.x;
          yv[i*8 + j*4 + rr*2 + 1] = v.y;
          writeA2(smp, row, c, v.x, v.y);
        }

    int gc = 0;
    prefetch(smb, 0, tid);
    prefetch(smb, 1, tid);

    float acc[16][4];

    #pragma unroll 1
    for (int pair = 0; pair < 32; pair++){
        int l = pair >> 1, net = pair & 1;
        const float* b0 = (net ? sb0 : lb0) + l*NHID;
        const float* b1 = (net ? sb1 : lb1) + l*NHID;
        const float* b2 = (net ? sb2 : lb2) + l*DIM;

        // ---- stage0: K=64 ----
        run_stage<4,64,12288>(acc, smb, smp, gc, wm, wn, lane, tid);
        #pragma unroll
        for (int i = 0; i < 2; i++)
          #pragma unroll
          for (int j = 0; j < 8; j++){
            int c = cb + j*8;
            float2 bb = *(const float2*)(b0 + c);
            float* d = acc[i*8 + j];
            writeA2(smp, r0 + i*16,     c, fmaxf(d[0]+bb.x,0.f), fmaxf(d[1]+bb.y,0.f));
            writeA2(smp, r0 + i*16 + 8, c, fmaxf(d[2]+bb.x,0.f), fmaxf(d[3]+bb.y,0.f));
          }

        // ---- stage1: K=256 ----
        run_stage<16,64,12288>(acc, smb, smp, gc, wm, wn, lane, tid);
        #pragma unroll
        for (int i = 0; i < 2; i++)
          #pragma unroll
          for (int j = 0; j < 8; j++){
            int c = cb + j*8;
            float2 bb = *(const float2*)(b1 + c);
            float* d = acc[i*8 + j];
            writeA2(smp, r0 + i*16,     c, fmaxf(d[0]+bb.x,0.f), fmaxf(d[1]+bb.y,0.f));
            writeA2(smp, r0 + i*16 + 8, c, fmaxf(d[2]+bb.x,0.f), fmaxf(d[3]+bb.y,0.f));
          }

        // ---- stage2: K=256, N=64 ----
        run_stage<16,16,3072>(acc, smb, smp, gc, wm, wn, lane, tid);
        if (net == 0){
            // loc -> smem; restore y tiles into A cols 0..63
            #pragma unroll
            for (int i = 0; i < 2; i++)
              #pragma unroll
              for (int j = 0; j < 2; j++){
                int c = cb2 + j*8;
                float2 bb = *(const float2*)(b2 + c);
                float* d = acc[i*8 + j];
                int ra = r0 + i*16, rb = ra + 8;
                *(float2*)&loc_sm[ra*66 + c] = make_float2(d[0]+bb.x, d[1]+bb.y);
                *(float2*)&loc_sm[rb*66 + c] = make_float2(d[2]+bb.x, d[3]+bb.y);
                int base = i*8 + j*4;
                writeA2(smp, ra, c, yv[base],     yv[base+1]);
                writeA2(smp, rb, c, yv[base+2],   yv[base+3]);
              }
        } else {
            // coupling: y = exp(-sc) * (y - loc)
            #pragma unroll
            for (int i = 0; i < 2; i++)
              #pragma unroll
              for (int j = 0; j < 2; j++){
                int c = cb2 + j*8;
                float2 bb = *(const float2*)(b2 + c);
                float* d = acc[i*8 + j];
                #pragma unroll
                for (int rr = 0; rr < 2; rr++){
                  int row = r0 + i*16 + rr*8;
                  float2 lc = *(const float2*)&loc_sm[row*66 + c];
                  int base = i*8 + j*4 + rr*2;
                  float y0 = expf(-(d[rr*2]  + bb.x)) * (yv[base]   - lc.x);
                  float y1 = expf(-(d[rr*2+1]+ bb.y)) * (yv[base+1] - lc.y);
                  yv[base] = y0; yv[base+1] = y1;
                  if (pair == 31)
                    *(float2*)(out + (size_t)(row0 + row)*DIM + c) = make_float2(y0, y1);
                  else
                    writeA2(smp, row, c, y0, y1);
                }
              }
        }
    }
    asm volatile("cp.async.wait_group 0;":::"memory");
}

// ---------------- launch ------------------------------------------------------
extern "C" void kernel_launch(void* const* d_in, const int* in_sizes, int n_in,
                              void* d_out, int out_size)
{
    const float* u   = (const float*)d_in[0];
    const float* lW0 = (const float*)d_in[1];
    const float* lb0 = (const float*)d_in[2];
    const float* lW1 = (const float*)d_in[3];
    const float* lb1 = (const float*)d_in[4];
    const float* lW2 = (const float*)d_in[5];
    const float* lb2 = (const float*)d_in[6];
    const float* sW0 = (const float*)d_in[7];
    const float* sb0 = (const float*)d_in[8];
    const float* sW1 = (const float*)d_in[9];
    const float* sb1 = (const float*)d_in[10];
    const float* sW2 = (const float*)d_in[11];
    const float* sb2 = (const float*)d_in[12];
    const float* M0  = (const float*)d_in[13];
    const float* M1  = (const float*)d_in[14];
    const float* M2  = (const float*)d_in[15];

    int rows = in_sizes[0] / DIM;

    cudaFuncSetAttribute(flow_kernel, cudaFuncAttributeMaxDynamicSharedMemorySize, SM_TOTAL);

    const int total = 32*WNET;
    prep_kernel<<<(total + 255)/256, 256>>>(lW0, lW1, lW2, sW0, sW1, sW2, M0, M1, M2);

    flow_kernel<<<rows / TBR, NTHREADS, SM_TOTAL>>>(
        u, lb0, lb1, lb2, sb0, sb1, sb2, (float*)d_out);
}

// round 6
// speedup vs baseline: 3.2524x; 1.1109x over previous
#include <cuda_runtime.h>
#include <cuda_bf16.h>

typedef unsigned int u32;

#define DIM 64
#define NHID 256
#define W0_SZ (DIM*NHID)
#define W1_SZ (NHID*NHID)
#define W2_SZ (NHID*DIM)
#define WNET  (W0_SZ+W1_SZ+W2_SZ)

#define TBR 128
#define NTHREADS 512

// per-group (wn) weight stream: per pair = stage0 4*6144 + stage1 16*6144 + stage2 16*1536
#define GRP_PAIR 147456
#define GRP_STRIDE ((size_t)32*GRP_PAIR)   /* 4718592 */
#define NITEMS (32*56)                      /* 1792 items per group */

#define SM_W   0u          /* 4 groups x 4 slots x 3072 = 49152 */
#define SM_AHI 49152u      /* 128 x 512B swizzled bf16 tile */
#define SM_ALO 114688u
#define SM_LOC 180224u     /* 128 x 66 fp32 */
#define SM_TOTAL 214016u

__device__ __align__(16) unsigned char g_W[(size_t)4*GRP_STRIDE];

static __device__ __forceinline__ u32 s2u(const void* p){
  u32 a; asm("{ .reg .u64 t; cvta.to.shared.u64 t, %1; cvt.u32.u64 %0, t; }":"=r"(a):"l"(p)); return a;
}
static __device__ __forceinline__ void cp16(u32 sdst, const void* g){
  asm volatile("cp.async.cg.shared.global [%0], [%1], 16;"::"r"(sdst),"l"(g):"memory");
}
static __device__ __forceinline__ void ldsm4(u32* r, u32 a){
  asm volatile("ldmatrix.sync.aligned.m8n8.x4.shared.b16 {%0,%1,%2,%3}, [%4];"
    :"=r"(r[0]),"=r"(r[1]),"=r"(r[2]),"=r"(r[3]):"r"(a));
}
static __device__ __forceinline__ void mma_bf16(float* d, const u32* a, const u32* b){
  asm volatile("mma.sync.aligned.m16n8k16.row.col.f32.bf16.bf16.f32 "
    "{%0,%1,%2,%3}, {%4,%5,%6,%7}, {%8,%9}, {%0,%1,%2,%3};"
    :"+f"(d[0]),"+f"(d[1]),"+f"(d[2]),"+f"(d[3])
    :"r"(a[0]),"r"(a[1]),"r"(a[2]),"r"(a[3]),"r"(b[0]),"r"(b[1]));
}
static __device__ __forceinline__ u32 packbf(float lo, float hi){
  u32 r; asm("cvt.rn.bf16x2.f32 %0, %1, %2;":"=r"(r):"f"(hi),"f"(lo)); return r;
}
// write 2 consecutive cols (c,c+1) of one row into A hi/lo swizzled tiles
static __device__ __forceinline__ void writeA2(unsigned char* smp, int row, int c, float v0, float v1){
  u32 unit = (u32)c >> 3;
  u32 off = (u32)row*512u + (((unit ^ ((u32)row & 7u)) << 4) | (((u32)c & 7u) << 1));
  u32 h = packbf(v0, v1);
  float h0 = __uint_as_float(h << 16);
  float h1 = __uint_as_float(h & 0xFFFF0000u);
  u32 lo = packbf(v0 - h0, v1 - h1);
  *(u32*)(smp + SM_AHI + off) = h;
  *(u32*)(smp + SM_ALO + off) = lo;
}

// ---------- prep: mask, bf16 hi/lo split, per-group item-stream image --------
__global__ void prep_kernel(
    const float* __restrict__ lW0, const float* __restrict__ lW1, const float* __restrict__ lW2,
    const float* __restrict__ sW0, const float* __restrict__ sW1, const float* __restrict__ sW2,
    const float* __restrict__ M0,  const float* __restrict__ M1,  const float* __restrict__ M2)
{
    int idx = blockIdx.x*blockDim.x + threadIdx.x;
    if (idx >= 32*WNET) return;
    int pair = idx / WNET, off = idx % WNET;
    int l = pair >> 1, net = pair & 1;
    float w; size_t dst; int loff;
    if (off < W0_SZ){
        int n = off >> 6, k = off & 63;
        int s = l*W0_SZ + off;
        w = (net ? sW0[s] : lW0[s]) * M0[s];
        int wn = n >> 6, np = n & 63;
        dst = (size_t)wn*GRP_STRIDE + (size_t)pair*GRP_PAIR
            + (size_t)(k >> 4)*6144 + (size_t)np*48 + (size_t)(k & 15)*2;
        loff = 3072;
    } else if (off < W0_SZ + W1_SZ){
        int o = off - W0_SZ;
        int n = o >> 8, k = o & 255;
        int s = l*W1_SZ + o;
        w = (net ? sW1[s] : lW1[s]) * M1[s];
        int wn = n >> 6, np = n & 63;
        dst = (size_t)wn*GRP_STRIDE + (size_t)pair*GRP_PAIR
            + 24576 + (size_t)(k >> 4)*6144 + (size_t)np*48 + (size_t)(k & 15)*2;
        loff = 3072;
    } else {
        int o = off - W0_SZ - W1_SZ;
        int n = o >> 8, k = o & 255;
        int s = l*W2_SZ + o;
        w = (net ? sW2[s] : lW2[s]) * M2[s];
        int wn = n >> 4, np = n & 15;
        dst = (size_t)wn*GRP_STRIDE + (size_t)pair*GRP_PAIR
            + 122880 + (size_t)(k >> 4)*1536 + (size_t)np*48 + (size_t)(k & 15)*2;
        loff = 768;
    }
    __nv_bfloat16 hv = __float2bfloat16_rn(w);
    __nv_bfloat16 lv = __float2bfloat16_rn(w - __bfloat162float(hv));
    *(__nv_bfloat16*)(g_W + dst) = hv;
    *(__nv_bfloat16*)(g_W + dst + loff) = lv;
}

// ---------------- fused flow kernel ------------------------------------------
__global__ void __launch_bounds__(NTHREADS,1) flow_kernel(
    const float* __restrict__ u,
    const float* __restrict__ lb0, const float* __restrict__ lb1, const float* __restrict__ lb2,
    const float* __restrict__ sb0, const float* __restrict__ sb1, const float* __restrict__ sb2,
    float* __restrict__ out)
{
    extern __shared__ unsigned char smp[];
    u32 smb = s2u(smp);
    int tid = threadIdx.x, lane = tid & 31, wid = tid >> 5;
    int wm = wid >> 2, wn = wid & 3;
    int gt = wm*32 + lane;          // thread index within wn-group
    int q = lane >> 3, ln = lane & 7;
    int row0 = blockIdx.x * TBR;
    float* loc_sm = (float*)(smp + SM_LOC);

    int r0  = wm*32 + (lane >> 2);
    int cb  = wn*64 + (lane & 3)*2;   // stage0/1 col base (N=256)
    int cb2 = wn*16 + (lane & 3)*2;   // stage2 col base (N=64)

    // init y regs + A tiles (cols 0..63)
    float yv[16];
    #pragma unroll
    for (int i = 0; i < 2; i++)
      #pragma unroll
      for (int j = 0; j < 2; j++)
        #pragma unroll
        for (int rr = 0; rr < 2; rr++){
          int row = r0 + i*16 + rr*8;
          int c = cb2 + j*8;
          float2 v = *(const float2*)(u + (size_t)(row0 + row)*DIM + c);
          yv[i*8 + j*4 + rr*2]     = v.x;
          yv[i*8 + j*4 + rr*2 + 1] = v.y;
          writeA2(smp, row, c, v.x, v.y);
        }

    // per-group weight pipeline state
    u32 wbase = smb + SM_W + (u32)wn*12288u;
    const unsigned char* gptr = g_W + (size_t)wn*GRP_STRIDE;
    int pf = 0, ci = 0, pfp = 0;

    auto pfetch = [&](){
        if (pf < NITEMS){
            int bytes = (pfp < 40) ? 3072 : 1536;
            u32 dst = wbase + (u32)(pf & 3)*3072u;
            int o = gt*16;
            if (bytes == 3072){
                cp16(dst + o, gptr + o);
                if (gt < 64) cp16(dst + 2048 + o, gptr + 2048 + o);
            } else if (gt < 96){
                cp16(dst + o, gptr + o);
            }
            gptr += bytes;
            if (++pfp == 56) pfp = 0;
        }
        asm volatile("cp.async.commit_group;":::"memory");
        pf++;
    };
    auto step = [&]() -> u32 {
        asm volatile("cp.async.wait_group 2;":::"memory");
        asm volatile("bar.sync %0, %1;"::"r"(1 + wn),"r"(128):"memory");
        pfetch();
        u32 s = wbase + (u32)(ci & 3)*3072u;
        ci++;
        return s;
    };

    pfetch(); pfetch(); pfetch();
    __syncthreads();   // initial A tiles visible to all warps

    float acc[16][4];
    auto zacc = [&](){
        #pragma unroll
        for (int t = 0; t < 16; t++){ acc[t][0]=0.f; acc[t][1]=0.f; acc[t][2]=0.f; acc[t][3]=0.f; }
    };
    auto ldA = [&](u32 base, int kc, u32 (*r)[4]){
        u32 arow0 = (u32)(wm*32 + ((q & 1) << 3) + ln);
        u32 aunit = (u32)(kc*2 + (q >> 1));
        #pragma unroll
        for (int i = 0; i < 2; i++){
            u32 rr = arow0 + (u32)i*16u;
            u32 aoff = rr*512u + ((aunit ^ (rr & 7u)) << 4);
            ldsm4(r[i], base + aoff);
        }
    };
    auto big_chunk = [&](int kc){
        u32 s = step();
        u32 ah[2][4], al[2][4];
        ldA(smb + SM_AHI, kc, ah);
        ldA(smb + SM_ALO, kc, al);
        #pragma unroll
        for (int g = 0; g < 4; g++){
            u32 boff = (u32)((g*16 + ((q >> 1) << 3) + ln)*48 + ((q & 1) << 4));
            u32 bh[4]; ldsm4(bh, s + boff);
            #pragma unroll
            for (int i = 0; i < 2; i++)
              #pragma unroll
              for (int tt = 0; tt < 2; tt++){
                float* d = acc[i*8 + g*2 + tt];
                mma_bf16(d, ah[i], bh + tt*2);
                mma_bf16(d, al[i], bh + tt*2);
              }
        }
        s = step();
        #pragma unroll
        for (int g = 0; g < 4; g++){
            u32 boff = (u32)((g*16 + ((q >> 1) << 3) + ln)*48 + ((q & 1) << 4));
            u32 bl[4]; ldsm4(bl, s + boff);
            #pragma unroll
            for (int i = 0; i < 2; i++)
              #pragma unroll
              for (int tt = 0; tt < 2; tt++)
                mma_bf16(acc[i*8 + g*2 + tt], ah[i], bl + tt*2);
        }
    };
    auto small_chunk = [&](int kc){
        u32 s = step();
        u32 ah[2][4], al[2][4];
        ldA(smb + SM_AHI, kc, ah);
        ldA(smb + SM_ALO, kc, al);
        u32 boff = (u32)((((q >> 1) << 3) + ln)*48 + ((q & 1) << 4));
        u32 bh[4], bl[4];
        ldsm4(bh, s + boff);
        ldsm4(bl, s + 768 + boff);
        #pragma unroll
        for (int i = 0; i < 2; i++)
          #pragma unroll
          for (int tt = 0; tt < 2; tt++){
            float* d = acc[i*8 + tt];
            mma_bf16(d, ah[i], bh + tt*2);
            mma_bf16(d, al[i], bh + tt*2);
            mma_bf16(d, ah[i], bl + tt*2);
          }
    };

    #pragma unroll 1
    for (int pair = 0; pair < 32; pair++){
        int l = pair >> 1, net = pair & 1;
        const float* b0 = (net ? sb0 : lb0) + l*NHID;
        const float* b1 = (net ? sb1 : lb1) + l*NHID;
        const float* b2 = (net ? sb2 : lb2) + l*DIM;

        // ---- stage0: K=64 ----
        zacc();
        #pragma unroll 1
        for (int kc = 0; kc < 4; kc++) big_chunk(kc);
        __syncthreads();
        #pragma unroll
        for (int i = 0; i < 2; i++)
          #pragma unroll
          for (int j = 0; j < 8; j++){
            int c = cb + j*8;
            float2 bb = *(const float2*)(b0 + c);
            float* d = acc[i*8 + j];
            writeA2(smp, r0 + i*16,     c, fmaxf(d[0]+bb.x,0.f), fmaxf(d[1]+bb.y,0.f));
            writeA2(smp, r0 + i*16 + 8, c, fmaxf(d[2]+bb.x,0.f), fmaxf(d[3]+bb.y,0.f));
          }
        __syncthreads();

        // ---- stage1: K=256 ----
        zacc();
        #pragma unroll 1
        for (int kc = 0; kc < 16; kc++) big_chunk(kc);
        __syncthreads();
        #pragma unroll
        for (int i = 0; i < 2; i++)
          #pragma unroll
          for (int j = 0; j < 8; j++){
            int c = cb + j*8;
            float2 bb = *(const float2*)(b1 + c);
            float* d = acc[i*8 + j];
            writeA2(smp, r0 + i*16,     c, fmaxf(d[0]+bb.x,0.f), fmaxf(d[1]+bb.y,0.f));
            writeA2(smp, r0 + i*16 + 8, c, fmaxf(d[2]+bb.x,0.f), fmaxf(d[3]+bb.y,0.f));
          }
        __syncthreads();

        // ---- stage2: K=256, N=64 ----
        zacc();
        #pragma unroll 1
        for (int kc = 0; kc < 16; kc++) small_chunk(kc);
        __syncthreads();
        if (net == 0){
            #pragma unroll
            for (int i = 0; i < 2; i++)
              #pragma unroll
              for (int j = 0; j < 2; j++){
                int c = cb2 + j*8;
                float2 bb = *(const float2*)(b2 + c);
                float* d = acc[i*8 + j];
                int ra = r0 + i*16, rb = ra + 8;
                *(float2*)&loc_sm[ra*66 + c] = make_float2(d[0]+bb.x, d[1]+bb.y);
                *(float2*)&loc_sm[rb*66 + c] = make_float2(d[2]+bb.x, d[3]+bb.y);
                int base = i*8 + j*4;
                writeA2(smp, ra, c, yv[base],   yv[base+1]);
                writeA2(smp, rb, c, yv[base+2], yv[base+3]);
              }
        } else {
            #pragma unroll
            for (int i = 0; i < 2; i++)
              #pragma unroll
              for (int j = 0; j < 2; j++){
                int c = cb2 + j*8;
                float2 bb = *(const float2*)(b2 + c);
                float* d = acc[i*8 + j];
                #pragma unroll
                for (int rr = 0; rr < 2; rr++){
                  int row = r0 + i*16 + rr*8;
                  float2 lc = *(const float2*)&loc_sm[row*66 + c];
                  int base = i*8 + j*4 + rr*2;
                  float y0 = expf(-(d[rr*2]  + bb.x)) * (yv[base]   - lc.x);
                  float y1 = expf(-(d[rr*2+1]+ bb.y)) * (yv[base+1] - lc.y);
                  yv[base] = y0; yv[base+1] = y1;
                  if (pair == 31)
                    *(float2*)(out + (size_t)(row0 + row)*DIM + c) = make_float2(y0, y1);
                  else
                    writeA2(smp, row, c, y0, y1);
                }
              }
        }
        __syncthreads();
    }
    asm volatile("cp.async.wait_group 0;":::"memory");
}

// ---------------- launch ------------------------------------------------------
extern "C" void kernel_launch(void* const* d_in, const int* in_sizes, int n_in,
                              void* d_out, int out_size)
{
    const float* u   = (const float*)d_in[0];
    const float* lW0 = (const float*)d_in[1];
    const float* lb0 = (const float*)d_in[2];
    const float* lW1 = (const float*)d_in[3];
    const float* lb1 = (const float*)d_in[4];
    const float* lW2 = (const float*)d_in[5];
    const float* lb2 = (const float*)d_in[6];
    const float* sW0 = (const float*)d_in[7];
    const float* sb0 = (const float*)d_in[8];
    const float* sW1 = (const float*)d_in[9];
    const float* sb1 = (const float*)d_in[10];
    const float* sW2 = (const float*)d_in[11];
    const float* sb2 = (const float*)d_in[12];
    const float* M0  = (const float*)d_in[13];
    const float* M1  = (const float*)d_in[14];
    const float* M2  = (const float*)d_in[15];

    int rows = in_sizes[0] / DIM;

    cudaFuncSetAttribute(flow_kernel, cudaFuncAttributeMaxDynamicSharedMemorySize, SM_TOTAL);

    const int total = 32*WNET;
    prep_kernel<<<(total + 255)/256, 256>>>(lW0, lW1, lW2, sW0, sW1, sW2, M0, M1, M2);

    flow_kernel<<<rows / TBR, NTHREADS, SM_TOTAL>>>(
        u, lb0, lb1, lb2, sb0, sb1, sb2, (float*)d_out);
}

// round 7
// speedup vs baseline: 3.4810x; 1.0703x over previous
#include <cuda_runtime.h>
#include <cuda_bf16.h>

typedef unsigned int u32;

#define DIM 64
#define NHID 256
#define W0_SZ (DIM*NHID)
#define W1_SZ (NHID*NHID)
#define W2_SZ (NHID*DIM)
#define WNET  (W0_SZ+W1_SZ+W2_SZ)

#define TBR 128
#define NTHREADS 512

// fragment-packed weight stream, per wn-group:
// per pair: stage0 4 chunks x (hi2048+lo2048) + stage1 16 x 4096 + stage2 16 x (hi512+lo512)
#define GRP_PAIR 98304
#define GRP_STRIDE ((size_t)32*GRP_PAIR)    /* 3145728 */

#define SM_AHI 0u          /* 128 x 512B swizzled bf16 tile */
#define SM_ALO 65536u
#define SM_LOC 131072u     /* 128 x 66 fp32 */
#define SM_Y   164864u     /* 128 x 66 fp32 */
#define SM_TOTAL 198656u

__device__ __align__(16) unsigned char g_W[(size_t)4*GRP_STRIDE];

static __device__ __forceinline__ u32 s2u(const void* p){
  u32 a; asm("{ .reg .u64 t; cvta.to.shared.u64 t, %1; cvt.u32.u64 %0, t; }":"=r"(a):"l"(p)); return a;
}
static __device__ __forceinline__ void ldsm4(u32* r, u32 a){
  asm volatile("ldmatrix.sync.aligned.m8n8.x4.shared.b16 {%0,%1,%2,%3}, [%4];"
    :"=r"(r[0]),"=r"(r[1]),"=r"(r[2]),"=r"(r[3]):"r"(a));
}
static __device__ __forceinline__ void mma_bf16(float* d, const u32* a, const u32* b){
  asm volatile("mma.sync.aligned.m16n8k16.row.col.f32.bf16.bf16.f32 "
    "{%0,%1,%2,%3}, {%4,%5,%6,%7}, {%8,%9}, {%0,%1,%2,%3};"
    :"+f"(d[0]),"+f"(d[1]),"+f"(d[2]),"+f"(d[3])
    :"r"(a[0]),"r"(a[1]),"r"(a[2]),"r"(a[3]),"r"(b[0]),"r"(b[1]));
}
static __device__ __forceinline__ u32 packbf(float lo, float hi){
  u32 r; asm("cvt.rn.bf16x2.f32 %0, %1, %2;":"=r"(r):"f"(hi),"f"(lo)); return r;
}
// write 2 consecutive cols (c,c+1) of one row into A hi/lo swizzled tiles
static __device__ __forceinline__ void writeA2(unsigned char* smp, int row, int c, float v0, float v1){
  u32 unit = (u32)c >> 3;
  u32 off = (u32)row*512u + (((unit ^ ((u32)row & 7u)) << 4) | (((u32)c & 7u) << 1));
  u32 h = packbf(v0, v1);
  float h0 = __uint_as_float(h << 16);
  float h1 = __uint_as_float(h & 0xFFFF0000u);
  u32 lo = packbf(v0 - h0, v1 - h1);
  *(u32*)(smp + SM_AHI + off) = h;
  *(u32*)(smp + SM_ALO + off) = lo;
}

// ---------- prep: mask, bf16 hi/lo split, mma-fragment-order image -----------
// For lane T, B-reg b of tile (g, tt): element B[n][k] with
//   n = nbase + g*16 + tt*8 + T/4,  k = kc*16 + (b&1)*8 + 2*(T%4) + byte/2
__global__ void prep_kernel(
    const float* __restrict__ lW0, const float* __restrict__ lW1, const float* __restrict__ lW2,
    const float* __restrict__ sW0, const float* __restrict__ sW1, const float* __restrict__ sW2,
    const float* __restrict__ M0,  const float* __restrict__ M1,  const float* __restrict__ M2)
{
    int idx = blockIdx.x*blockDim.x + threadIdx.x;
    if (idx >= 32*WNET) return;
    int pair = idx / WNET, off = idx % WNET;
    int l = pair >> 1, net = pair & 1;
    float w; int n, k, wn, nl, itemoff, lodelta;
    if (off < W0_SZ){
        n = off >> 6; k = off & 63;
        int s = l*W0_SZ + off;
        w = (net ? sW0[s] : lW0[s]) * M0[s];
        wn = n >> 6; nl = n & 63;
        itemoff = (k >> 4)*4096; lodelta = 2048;
    } else if (off < W0_SZ + W1_SZ){
        int o = off - W0_SZ;
        n = o >> 8; k = o & 255;
        int s = l*W1_SZ + o;
        w = (net ? sW1[s] : lW1[s]) * M1[s];
        wn = n >> 6; nl = n & 63;
        itemoff = 16384 + (k >> 4)*4096; lodelta = 2048;
    } else {
        int o = off - W0_SZ - W1_SZ;
        n = o >> 8; k = o & 255;
        int s = l*W2_SZ + o;
        w = (net ? sW2[s] : lW2[s]) * M2[s];
        wn = n >> 4; nl = n & 15;
        itemoff = 81920 + (k >> 4)*1024; lodelta = 512;
    }
    int g = nl >> 4, nn = nl & 15, tt = nn >> 3, nrow = nn & 7, kl = k & 15;
    int T = (nrow << 2) | ((kl & 7) >> 1);
    int b = (tt << 1) | (kl >> 3);
    size_t dst = (size_t)wn*GRP_STRIDE + (size_t)pair*GRP_PAIR
               + itemoff + g*512 + T*16 + b*4 + ((kl & 1) << 1);
    __nv_bfloat16 hv = __float2bfloat16_rn(w);
    __nv_bfloat16 lv = __float2bfloat16_rn(w - __bfloat162float(hv));
    *(__nv_bfloat16*)(g_W + dst) = hv;
    *(__nv_bfloat16*)(g_W + dst + lodelta) = lv;
}

// ---------------- fused flow kernel ------------------------------------------
__global__ void __launch_bounds__(NTHREADS,1) flow_kernel(
    const float* __restrict__ u,
    const float* __restrict__ lb0, const float* __restrict__ lb1, const float* __restrict__ lb2,
    const float* __restrict__ sb0, const float* __restrict__ sb1, const float* __restrict__ sb2,
    float* __restrict__ out)
{
    extern __shared__ unsigned char smp[];
    u32 smb = s2u(smp);
    int tid = threadIdx.x, lane = tid & 31, wid = tid >> 5;
    int wm = wid >> 2, wn = wid & 3;
    int q = lane >> 3, ln = lane & 7;
    int row0 = blockIdx.x * TBR;
    float* loc_sm = (float*)(smp + SM_LOC);
    float* y_sm   = (float*)(smp + SM_Y);

    int r0  = wm*32 + (lane >> 2);
    int cb  = wn*64 + (lane & 3)*2;   // stage0/1 col base (N=256)
    int cb2 = wn*16 + (lane & 3)*2;   // stage2 col base (N=64)

    // per-thread weight stream base (fragment order: this lane's 16B slices)
    const unsigned char* tb = g_W + (size_t)wn*GRP_STRIDE + (size_t)lane*16;

    // init y smem + A tiles (cols 0..63)
    #pragma unroll
    for (int i = 0; i < 2; i++)
      #pragma unroll
      for (int j = 0; j < 2; j++)
        #pragma unroll
        for (int rr = 0; rr < 2; rr++){
          int row = r0 + i*16 + rr*8;
          int c = cb2 + j*8;
          float2 v = *(const float2*)(u + (size_t)(row0 + row)*DIM + c);
          *(float2*)&y_sm[row*66 + c] = v;
          writeA2(smp, row, c, v.x, v.y);
        }
    __syncthreads();

    float acc[16][4];
    auto zacc = [&](){
        #pragma unroll
        for (int t = 0; t < 16; t++){ acc[t][0]=0.f; acc[t][1]=0.f; acc[t][2]=0.f; acc[t][3]=0.f; }
    };
    auto ldA = [&](u32 base, int kc, u32 (*r)[4]){
        u32 arow0 = (u32)(wm*32 + ((q & 1) << 3) + ln);
        u32 aunit = (u32)(kc*2 + (q >> 1));
        #pragma unroll
        for (int i = 0; i < 2; i++){
            u32 rr = arow0 + (u32)i*16u;
            u32 aoff = rr*512u + ((aunit ^ (rr & 7u)) << 4);
            ldsm4(r[i], base + aoff);
        }
    };
    auto big_chunk = [&](const unsigned char* wp, int kc){
        uint4 bh[4], bl[4];
        #pragma unroll
        for (int g = 0; g < 4; g++) bh[g] = *(const uint4*)(wp + g*512);
        #pragma unroll
        for (int g = 0; g < 4; g++) bl[g] = *(const uint4*)(wp + 2048 + g*512);
        u32 ah[2][4], al[2][4];
        ldA(smb + SM_AHI, kc, ah);
        ldA(smb + SM_ALO, kc, al);
        #pragma unroll
        for (int g = 0; g < 4; g++){
            const u32* bp = (const u32*)&bh[g];
            #pragma unroll
            for (int i = 0; i < 2; i++)
              #pragma unroll
              for (int tt = 0; tt < 2; tt++){
                float* d = acc[i*8 + g*2 + tt];
                mma_bf16(d, ah[i], bp + tt*2);
                mma_bf16(d, al[i], bp + tt*2);
              }
        }
        #pragma unroll
        for (int g = 0; g < 4; g++){
            const u32* bp = (const u32*)&bl[g];
            #pragma unroll
            for (int i = 0; i < 2; i++)
              #pragma unroll
              for (int tt = 0; tt < 2; tt++)
                mma_bf16(acc[i*8 + g*2 + tt], ah[i], bp + tt*2);
        }
    };
    auto small_chunk = [&](const unsigned char* wp, int kc){
        uint4 bh = *(const uint4*)(wp);
        uint4 bl = *(const uint4*)(wp + 512);
        u32 ah[2][4], al[2][4];
        ldA(smb + SM_AHI, kc, ah);
        ldA(smb + SM_ALO, kc, al);
        const u32* bhp = (const u32*)&bh;
        const u32* blp = (const u32*)&bl;
        #pragma unroll
        for (int i = 0; i < 2; i++)
          #pragma unroll
          for (int tt = 0; tt < 2; tt++){
            float* d = acc[i*8 + tt];
            mma_bf16(d, ah[i], bhp + tt*2);
            mma_bf16(d, al[i], bhp + tt*2);
            mma_bf16(d, ah[i], blp + tt*2);
          }
    };

    #pragma unroll 1
    for (int pair = 0; pair < 32; pair++){
        int l = pair >> 1, net = pair & 1;
        const float* b0 = (net ? sb0 : lb0) + l*NHID;
        const float* b1 = (net ? sb1 : lb1) + l*NHID;
        const float* b2 = (net ? sb2 : lb2) + l*DIM;
        const unsigned char* wp0 = tb + (size_t)pair*GRP_PAIR;

        // ---- stage0: K=64 ----
        zacc();
        #pragma unroll 1
        for (int kc = 0; kc < 4; kc++) big_chunk(wp0 + kc*4096, kc);
        __syncthreads();
        #pragma unroll
        for (int i = 0; i < 2; i++)
          #pragma unroll
          for (int j = 0; j < 8; j++){
            int c = cb + j*8;
            float2 bb = *(const float2*)(b0 + c);
            float* d = acc[i*8 + j];
            writeA2(smp, r0 + i*16,     c, fmaxf(d[0]+bb.x,0.f), fmaxf(d[1]+bb.y,0.f));
            writeA2(smp, r0 + i*16 + 8, c, fmaxf(d[2]+bb.x,0.f), fmaxf(d[3]+bb.y,0.f));
          }
        __syncthreads();

        // ---- stage1: K=256 ----
        zacc();
        #pragma unroll 1
        for (int kc = 0; kc < 16; kc++) big_chunk(wp0 + 16384 + kc*4096, kc);
        __syncthreads();
        #pragma unroll
        for (int i = 0; i < 2; i++)
          #pragma unroll
          for (int j = 0; j < 8; j++){
            int c = cb + j*8;
            float2 bb = *(const float2*)(b1 + c);
            float* d = acc[i*8 + j];
            writeA2(smp, r0 + i*16,     c, fmaxf(d[0]+bb.x,0.f), fmaxf(d[1]+bb.y,0.f));
            writeA2(smp, r0 + i*16 + 8, c, fmaxf(d[2]+bb.x,0.f), fmaxf(d[3]+bb.y,0.f));
          }
        __syncthreads();

        // ---- stage2: K=256, N=64 ----
        zacc();
        #pragma unroll 1
        for (int kc = 0; kc < 16; kc++) small_chunk(wp0 + 81920 + kc*1024, kc);
        __syncthreads();
        if (net == 0){
            #pragma unroll
            for (int i = 0; i < 2; i++)
              #pragma unroll
              for (int j = 0; j < 2; j++){
                int c = cb2 + j*8;
                float2 bb = *(const float2*)(b2 + c);
                float* d = acc[i*8 + j];
                int ra = r0 + i*16, rb = ra + 8;
                *(float2*)&loc_sm[ra*66 + c] = make_float2(d[0]+bb.x, d[1]+bb.y);
                *(float2*)&loc_sm[rb*66 + c] = make_float2(d[2]+bb.x, d[3]+bb.y);
                float2 ya = *(const float2*)&y_sm[ra*66 + c];
                float2 yb = *(const float2*)&y_sm[rb*66 + c];
                writeA2(smp, ra, c, ya.x, ya.y);
                writeA2(smp, rb, c, yb.x, yb.y);
              }
        } else {
            #pragma unroll
            for (int i = 0; i < 2; i++)
              #pragma unroll
              for (int j = 0; j < 2; j++){
                int c = cb2 + j*8;
                float2 bb = *(const float2*)(b2 + c);
                float* d = acc[i*8 + j];
                #pragma unroll
                for (int rr = 0; rr < 2; rr++){
                  int row = r0 + i*16 + rr*8;
                  float2 lc = *(const float2*)&loc_sm[row*66 + c];
                  float2 yo = *(const float2*)&y_sm[row*66 + c];
                  float y0 = expf(-(d[rr*2]  + bb.x)) * (yo.x - lc.x);
                  float y1 = expf(-(d[rr*2+1]+ bb.y)) * (yo.y - lc.y);
                  if (pair == 31){
                    *(float2*)(out + (size_t)(row0 + row)*DIM + c) = make_float2(y0, y1);
                  } else {
                    *(float2*)&y_sm[row*66 + c] = make_float2(y0, y1);
                    writeA2(smp, row, c, y0, y1);
                  }
                }
              }
        }
        __syncthreads();
    }
}

// ---------------- launch ------------------------------------------------------
extern "C" void kernel_launch(void* const* d_in, const int* in_sizes, int n_in,
                              void* d_out, int out_size)
{
    const float* u   = (const float*)d_in[0];
    const float* lW0 = (const float*)d_in[1];
    const float* lb0 = (const float*)d_in[2];
    const float* lW1 = (const float*)d_in[3];
    const float* lb1 = (const float*)d_in[4];
    const float* lW2 = (const float*)d_in[5];
    const float* lb2 = (const float*)d_in[6];
    const float* sW0 = (const float*)d_in[7];
    const float* sb0 = (const float*)d_in[8];
    const float* sW1 = (const float*)d_in[9];
    const float* sb1 = (const float*)d_in[10];
    const float* sW2 = (const float*)d_in[11];
    const float* sb2 = (const float*)d_in[12];
    const float* M0  = (const float*)d_in[13];
    const float* M1  = (const float*)d_in[14];
    const float* M2  = (const float*)d_in[15];

    int rows = in_sizes[0] / DIM;

    cudaFuncSetAttribute(flow_kernel, cudaFuncAttributeMaxDynamicSharedMemorySize, SM_TOTAL);

    const int total = 32*WNET;
    prep_kernel<<<(total + 255)/256, 256>>>(lW0, lW1, lW2, sW0, sW1, sW2, M0, M1, M2);

    flow_kernel<<<rows / TBR, NTHREADS, SM_TOTAL>>>(
        u, lb0, lb1, lb2, sb0, sb1, sb2, (float*)d_out);
}

// round 8
// speedup vs baseline: 3.8950x; 1.1189x over previous
#include <cuda_runtime.h>
#include <cuda_bf16.h>

typedef unsigned int u32;

#define DIM 64
#define NHID 256
#define W0_SZ (DIM*NHID)
#define W1_SZ (NHID*NHID)
#define W2_SZ (NHID*DIM)
#define WNET  (W0_SZ+W1_SZ+W2_SZ)

#define TBR 128
#define NTHREADS 512

// fragment-packed weight stream, per wn-group:
// per pair: stage0 4 chunks x (hi2048+lo2048) + stage1 16 x 4096 + stage2 16 x (hi512+lo512)
#define GRP_PAIR 98304
#define GRP_STRIDE ((size_t)32*GRP_PAIR)    /* 3145728 */

#define SM_AHI 0u          /* 128 x 512B swizzled bf16 tile */
#define SM_ALO 65536u
#define SM_LOC 131072u     /* 128 x 66 fp32 */
#define SM_Y   164864u     /* 128 x 66 fp32 */
#define SM_TOTAL 198656u

// +4096 pad: register prefetch may read one item past the last pair
__device__ __align__(16) unsigned char g_W[(size_t)4*GRP_STRIDE + 4096];

static __device__ __forceinline__ u32 s2u(const void* p){
  u32 a; asm("{ .reg .u64 t; cvta.to.shared.u64 t, %1; cvt.u32.u64 %0, t; }":"=r"(a):"l"(p)); return a;
}
static __device__ __forceinline__ void ldsm4(u32* r, u32 a){
  asm volatile("ldmatrix.sync.aligned.m8n8.x4.shared.b16 {%0,%1,%2,%3}, [%4];"
    :"=r"(r[0]),"=r"(r[1]),"=r"(r[2]),"=r"(r[3]):"r"(a));
}
static __device__ __forceinline__ void mma_bf16(float* d, const u32* a, const u32* b){
  asm volatile("mma.sync.aligned.m16n8k16.row.col.f32.bf16.bf16.f32 "
    "{%0,%1,%2,%3}, {%4,%5,%6,%7}, {%8,%9}, {%0,%1,%2,%3};"
    :"+f"(d[0]),"+f"(d[1]),"+f"(d[2]),"+f"(d[3])
    :"r"(a[0]),"r"(a[1]),"r"(a[2]),"r"(a[3]),"r"(b[0]),"r"(b[1]));
}
static __device__ __forceinline__ u32 packbf(float lo, float hi){
  u32 r; asm("cvt.rn.bf16x2.f32 %0, %1, %2;":"=r"(r):"f"(hi),"f"(lo)); return r;
}
// write 2 consecutive cols (c,c+1) of one row into A hi/lo swizzled tiles
static __device__ __forceinline__ void writeA2(unsigned char* smp, int row, int c, float v0, float v1){
  u32 unit = (u32)c >> 3;
  u32 off = (u32)row*512u + (((unit ^ ((u32)row & 7u)) << 4) | (((u32)c & 7u) << 1));
  u32 h = packbf(v0, v1);
  float h0 = __uint_as_float(h << 16);
  float h1 = __uint_as_float(h & 0xFFFF0000u);
  u32 lo = packbf(v0 - h0, v1 - h1);
  *(u32*)(smp + SM_AHI + off) = h;
  *(u32*)(smp + SM_ALO + off) = lo;
}

// ---------- prep: mask, bf16 hi/lo split, mma-fragment-order image -----------
__global__ void prep_kernel(
    const float* __restrict__ lW0, const float* __restrict__ lW1, const float* __restrict__ lW2,
    const float* __restrict__ sW0, const float* __restrict__ sW1, const float* __restrict__ sW2,
    const float* __restrict__ M0,  const float* __restrict__ M1,  const float* __restrict__ M2)
{
    int idx = blockIdx.x*blockDim.x + threadIdx.x;
    if (idx >= 32*WNET) return;
    int pair = idx / WNET, off = idx % WNET;
    int l = pair >> 1, net = pair & 1;
    float w; int n, k, wn, nl, itemoff, lodelta;
    if (off < W0_SZ){
        n = off >> 6; k = off & 63;
        int s = l*W0_SZ + off;
        w = (net ? sW0[s] : lW0[s]) * M0[s];
        wn = n >> 6; nl = n & 63;
        itemoff = (k >> 4)*4096; lodelta = 2048;
    } else if (off < W0_SZ + W1_SZ){
        int o = off - W0_SZ;
        n = o >> 8; k = o & 255;
        int s = l*W1_SZ + o;
        w = (net ? sW1[s] : lW1[s]) * M1[s];
        wn = n >> 6; nl = n & 63;
        itemoff = 16384 + (k >> 4)*4096; lodelta = 2048;
    } else {
        int o = off - W0_SZ - W1_SZ;
        n = o >> 8; k = o & 255;
        int s = l*W2_SZ + o;
        w = (net ? sW2[s] : lW2[s]) * M2[s];
        wn = n >> 4; nl = n & 15;
        itemoff = 81920 + (k >> 4)*1024; lodelta = 512;
    }
    int g = nl >> 4, nn = nl & 15, tt = nn >> 3, nrow = nn & 7, kl = k & 15;
    int T = (nrow << 2) | ((kl & 7) >> 1);
    int b = (tt << 1) | (kl >> 3);
    size_t dst = (size_t)wn*GRP_STRIDE + (size_t)pair*GRP_PAIR
               + itemoff + g*512 + T*16 + b*4 + ((kl & 1) << 1);
    __nv_bfloat16 hv = __float2bfloat16_rn(w);
    __nv_bfloat16 lv = __float2bfloat16_rn(w - __bfloat162float(hv));
    *(__nv_bfloat16*)(g_W + dst) = hv;
    *(__nv_bfloat16*)(g_W + dst + lodelta) = lv;
}

// ---------------- fused flow kernel ------------------------------------------
__global__ void __launch_bounds__(NTHREADS,1) flow_kernel(
    const float* __restrict__ u,
    const float* __restrict__ lb0, const float* __restrict__ lb1, const float* __restrict__ lb2,
    const float* __restrict__ sb0, const float* __restrict__ sb1, const float* __restrict__ sb2,
    float* __restrict__ out)
{
    extern __shared__ unsigned char smp[];
    u32 smb = s2u(smp);
    int tid = threadIdx.x, lane = tid & 31, wid = tid >> 5;
    int wm = wid >> 2, wn = wid & 3;
    int q = lane >> 3, ln = lane & 7;
    int row0 = blockIdx.x * TBR;
    float* loc_sm = (float*)(smp + SM_LOC);
    float* y_sm   = (float*)(smp + SM_Y);

    int r0  = wm*32 + (lane >> 2);
    int cb  = wn*64 + (lane & 3)*2;   // stage0/1 col base (N=256)
    int cb2 = wn*16 + (lane & 3)*2;   // stage2 col base (N=64)

    // per-thread weight stream base (fragment order: this lane's 16B slices)
    const unsigned char* tb = g_W + (size_t)wn*GRP_STRIDE + (size_t)lane*16;

    // init y smem + A tiles (cols 0..63)
    #pragma unroll
    for (int i = 0; i < 2; i++)
      #pragma unroll
      for (int j = 0; j < 2; j++)
        #pragma unroll
        for (int rr = 0; rr < 2; rr++){
          int row = r0 + i*16 + rr*8;
          int c = cb2 + j*8;
          float2 v = *(const float2*)(u + (size_t)(row0 + row)*DIM + c);
          *(float2*)&y_sm[row*66 + c] = v;
          writeA2(smp, row, c, v.x, v.y);
        }
    __syncthreads();

    float acc[16][4];
    uint4 bh[4];
    auto zacc = [&](){
        #pragma unroll
        for (int t = 0; t < 16; t++){ acc[t][0]=0.f; acc[t][1]=0.f; acc[t][2]=0.f; acc[t][3]=0.f; }
    };
    auto ldA = [&](u32 base, int kc, u32 (*r)[4]){
        u32 arow0 = (u32)(wm*32 + ((q & 1) << 3) + ln);
        u32 aunit = (u32)(kc*2 + (q >> 1));
        #pragma unroll
        for (int i = 0; i < 2; i++){
            u32 rr = arow0 + (u32)i*16u;
            u32 aoff = rr*512u + ((aunit ^ (rr & 7u)) << 4);
            ldsm4(r[i], base + aoff);
        }
    };
    // big chunk: bh preloaded by caller/prefetch; prefetches next item's hi.
    // Per-acc accumulation order: ah*bh, al*bh, ah*bl (same as previous rounds).
    auto big_chunk = [&](const unsigned char* wp_cur, int kc){
        uint4 bl[4];
        #pragma unroll
        for (int g = 0; g < 4; g++) bl[g] = *(const uint4*)(wp_cur + 2048 + g*512);
        u32 ah[2][4], al[2][4];
        ldA(smb + SM_AHI, kc, ah);
        ldA(smb + SM_ALO, kc, al);
        // pass1: ah * bh (16 independent MMAs)
        #pragma unroll
        for (int g = 0; g < 4; g++){
            const u32* bp = (const u32*)&bh[g];
            #pragma unroll
            for (int i = 0; i < 2; i++)
              #pragma unroll
              for (int tt = 0; tt < 2; tt++)
                mma_bf16(acc[i*8 + g*2 + tt], ah[i], bp + tt*2);
        }
        // pass2: al * bh (16 independent)
        #pragma unroll
        for (int g = 0; g < 4; g++){
            const u32* bp = (const u32*)&bh[g];
            #pragma unroll
            for (int i = 0; i < 2; i++)
              #pragma unroll
              for (int tt = 0; tt < 2; tt++)
                mma_bf16(acc[i*8 + g*2 + tt], al[i], bp + tt*2);
        }
        // prefetch next item's bh (bh regs dead after pass2; covered by pass3)
        #pragma unroll
        for (int g = 0; g < 4; g++) bh[g] = *(const uint4*)(wp_cur + 4096 + g*512);
        // pass3: ah * bl (16 independent)
        #pragma unroll
        for (int g = 0; g < 4; g++){
            const u32* bp = (const u32*)&bl[g];
            #pragma unroll
            for (int i = 0; i < 2; i++)
              #pragma unroll
              for (int tt = 0; tt < 2; tt++)
                mma_bf16(acc[i*8 + g*2 + tt], ah[i], bp + tt*2);
        }
    };
    // small chunk (stage2): bh[0] preloaded; prefetches next item's hi
    auto small_chunk = [&](const unsigned char* wp_cur, int kc){
        uint4 bl = *(const uint4*)(wp_cur + 512);
        u32 ah[2][4], al[2][4];
        ldA(smb + SM_AHI, kc, ah);
        ldA(smb + SM_ALO, kc, al);
        const u32* bhp = (const u32*)&bh[0];
        const u32* blp = (const u32*)&bl;
        #pragma unroll
        for (int i = 0; i < 2; i++)
          #pragma unroll
          for (int tt = 0; tt < 2; tt++)
            mma_bf16(acc[i*8 + tt], ah[i], bhp + tt*2);
        #pragma unroll
        for (int i = 0; i < 2; i++)
          #pragma unroll
          for (int tt = 0; tt < 2; tt++)
            mma_bf16(acc[i*8 + tt], al[i], bhp + tt*2);
        bh[0] = *(const uint4*)(wp_cur + 1024);   // next small item's hi
        #pragma unroll
        for (int i = 0; i < 2; i++)
          #pragma unroll
          for (int tt = 0; tt < 2; tt++)
            mma_bf16(acc[i*8 + tt], ah[i], blp + tt*2);
    };

    #pragma unroll 1
    for (int pair = 0; pair < 32; pair++){
        int l = pair >> 1, net = pair & 1;
        const float* b0 = (net ? sb0 : lb0) + l*NHID;
        const float* b1 = (net ? sb1 : lb1) + l*NHID;
        const float* b2 = (net ? sb2 : lb2) + l*DIM;
        const unsigned char* wp0 = tb + (size_t)pair*GRP_PAIR;

        // preload bh for stage0 chunk0
        #pragma unroll
        for (int g = 0; g < 4; g++) bh[g] = *(const uint4*)(wp0 + g*512);

        // ---- stage0: K=64 ----
        zacc();
        #pragma unroll 1
        for (int kc = 0; kc < 4; kc++) big_chunk(wp0 + kc*4096, kc);
        __syncthreads();
        #pragma unroll
        for (int i = 0; i < 2; i++)
          #pragma unroll
          for (int j = 0; j < 8; j++){
            int c = cb + j*8;
            float2 bb = *(const float2*)(b0 + c);
            float* d = acc[i*8 + j];
            writeA2(smp, r0 + i*16,     c, fmaxf(d[0]+bb.x,0.f), fmaxf(d[1]+bb.y,0.f));
            writeA2(smp, r0 + i*16 + 8, c, fmaxf(d[2]+bb.x,0.f), fmaxf(d[3]+bb.y,0.f));
          }
        __syncthreads();

        // ---- stage1: K=256 ---- (bh already prefetched by stage0's last chunk)
        zacc();
        #pragma unroll 1
        for (int kc = 0; kc < 16; kc++) big_chunk(wp0 + 16384 + kc*4096, kc);
        __syncthreads();
        #pragma unroll
        for (int i = 0; i < 2; i++)
          #pragma unroll
          for (int j = 0; j < 8; j++){
            int c = cb + j*8;
            float2 bb = *(const float2*)(b1 + c);
            float* d = acc[i*8 + j];
            writeA2(smp, r0 + i*16,     c, fmaxf(d[0]+bb.x,0.f), fmaxf(d[1]+bb.y,0.f));
            writeA2(smp, r0 + i*16 + 8, c, fmaxf(d[2]+bb.x,0.f), fmaxf(d[3]+bb.y,0.f));
          }
        __syncthreads();

        // ---- stage2: K=256, N=64 ----
        zacc();
        bh[0] = *(const uint4*)(wp0 + 81920);   // stage2 chunk0 hi
        #pragma unroll 1
        for (int kc = 0; kc < 16; kc++) small_chunk(wp0 + 81920 + kc*1024, kc);
        __syncthreads();
        if (net == 0){
            #pragma unroll
            for (int i = 0; i < 2; i++)
              #pragma unroll
              for (int j = 0; j < 2; j++){
                int c = cb2 + j*8;
                float2 bb = *(const float2*)(b2 + c);
                float* d = acc[i*8 + j];
                int ra = r0 + i*16, rb = ra + 8;
                *(float2*)&loc_sm[ra*66 + c] = make_float2(d[0]+bb.x, d[1]+bb.y);
                *(float2*)&loc_sm[rb*66 + c] = make_float2(d[2]+bb.x, d[3]+bb.y);
                float2 ya = *(const float2*)&y_sm[ra*66 + c];
                float2 yb = *(const float2*)&y_sm[rb*66 + c];
                writeA2(smp, ra, c, ya.x, ya.y);
                writeA2(smp, rb, c, yb.x, yb.y);
              }
        } else {
            #pragma unroll
            for (int i = 0; i < 2; i++)
              #pragma unroll
              for (int j = 0; j < 2; j++){
                int c = cb2 + j*8;
                float2 bb = *(const float2*)(b2 + c);
                float* d = acc[i*8 + j];
                #pragma unroll
                for (int rr = 0; rr < 2; rr++){
                  int row = r0 + i*16 + rr*8;
                  float2 lc = *(const float2*)&loc_sm[row*66 + c];
                  float2 yo = *(const float2*)&y_sm[row*66 + c];
                  float y0 = expf(-(d[rr*2]  + bb.x)) * (yo.x - lc.x);
                  float y1 = expf(-(d[rr*2+1]+ bb.y)) * (yo.y - lc.y);
                  if (pair == 31){
                    *(float2*)(out + (size_t)(row0 + row)*DIM + c) = make_float2(y0, y1);
                  } else {
                    *(float2*)&y_sm[row*66 + c] = make_float2(y0, y1);
                    writeA2(smp, row, c, y0, y1);
                  }
                }
              }
        }
        __syncthreads();
    }
}

// ---------------- launch ------------------------------------------------------
extern "C" void kernel_launch(void* const* d_in, const int* in_sizes, int n_in,
                              void* d_out, int out_size)
{
    const float* u   = (const float*)d_in[0];
    const float* lW0 = (const float*)d_in[1];
    const float* lb0 = (const float*)d_in[2];
    const float* lW1 = (const float*)d_in[3];
    const float* lb1 = (const float*)d_in[4];
    const float* lW2 = (const float*)d_in[5];
    const float* lb2 = (const float*)d_in[6];
    const float* sW0 = (const float*)d_in[7];
    const float* sb0 = (const float*)d_in[8];
    const float* sW1 = (const float*)d_in[9];
    const float* sb1 = (const float*)d_in[10];
    const float* sW2 = (const float*)d_in[11];
    const float* sb2 = (const float*)d_in[12];
    const float* M0  = (const float*)d_in[13];
    const float* M1  = (const float*)d_in[14];
    const float* M2  = (const float*)d_in[15];

    int rows = in_sizes[0] / DIM;

    cudaFuncSetAttribute(flow_kernel, cudaFuncAttributeMaxDynamicSharedMemorySize, SM_TOTAL);

    const int total = 32*WNET;
    prep_kernel<<<(total + 255)/256, 256>>>(lW0, lW1, lW2, sW0, sW1, sW2, M0, M1, M2);

    flow_kernel<<<rows / TBR, NTHREADS, SM_TOTAL>>>(
        u, lb0, lb1, lb2, sb0, sb1, sb2, (float*)d_out);
}

// round 9
// speedup vs baseline: 4.0246x; 1.0333x over previous
#include <cuda_runtime.h>
#include <cuda_bf16.h>

typedef unsigned int u32;

#define DIM 64
#define NHID 256
#define W0_SZ (DIM*NHID)
#define W1_SZ (NHID*NHID)
#define W2_SZ (NHID*DIM)
#define WNET  (W0_SZ+W1_SZ+W2_SZ)

#define TBR 64
#define NTHREADS 256

// fragment-packed weight stream, per wn-group:
// per pair: stage0 4 chunks x (hi2048+lo2048) + stage1 16 x 4096 + stage2 16 x (hi512+lo512)
#define GRP_PAIR 98304
#define GRP_STRIDE ((size_t)32*GRP_PAIR)    /* 3145728 */

#define SM_AHI 0u          /* 64 x 512B swizzled bf16 tile */
#define SM_ALO 32768u
#define SM_LOC 65536u      /* 64 x 66 fp32 */
#define SM_Y   82432u      /* 64 x 66 fp32 */
#define SM_TOTAL 99328u

// +4096 pad: register prefetch may read one item past the last pair
__device__ __align__(16) unsigned char g_W[(size_t)4*GRP_STRIDE + 4096];

static __device__ __forceinline__ u32 s2u(const void* p){
  u32 a; asm("{ .reg .u64 t; cvta.to.shared.u64 t, %1; cvt.u32.u64 %0, t; }":"=r"(a):"l"(p)); return a;
}
static __device__ __forceinline__ void ldsm4(u32* r, u32 a){
  asm volatile("ldmatrix.sync.aligned.m8n8.x4.shared.b16 {%0,%1,%2,%3}, [%4];"
    :"=r"(r[0]),"=r"(r[1]),"=r"(r[2]),"=r"(r[3]):"r"(a));
}
static __device__ __forceinline__ void mma_bf16(float* d, const u32* a, const u32* b){
  asm volatile("mma.sync.aligned.m16n8k16.row.col.f32.bf16.bf16.f32 "
    "{%0,%1,%2,%3}, {%4,%5,%6,%7}, {%8,%9}, {%0,%1,%2,%3};"
    :"+f"(d[0]),"+f"(d[1]),"+f"(d[2]),"+f"(d[3])
    :"r"(a[0]),"r"(a[1]),"r"(a[2]),"r"(a[3]),"r"(b[0]),"r"(b[1]));
}
static __device__ __forceinline__ u32 packbf(float lo, float hi){
  u32 r; asm("cvt.rn.bf16x2.f32 %0, %1, %2;":"=r"(r):"f"(hi),"f"(lo)); return r;
}
// write 2 consecutive cols (c,c+1) of one row into A hi/lo swizzled tiles
static __device__ __forceinline__ void writeA2(unsigned char* smp, int row, int c, float v0, float v1){
  u32 unit = (u32)c >> 3;
  u32 off = (u32)row*512u + (((unit ^ ((u32)row & 7u)) << 4) | (((u32)c & 7u) << 1));
  u32 h = packbf(v0, v1);
  float h0 = __uint_as_float(h << 16);
  float h1 = __uint_as_float(h & 0xFFFF0000u);
  u32 lo = packbf(v0 - h0, v1 - h1);
  *(u32*)(smp + SM_AHI + off) = h;
  *(u32*)(smp + SM_ALO + off) = lo;
}

// ---------- prep: mask, bf16 hi/lo split, mma-fragment-order image -----------
__global__ void prep_kernel(
    const float* __restrict__ lW0, const float* __restrict__ lW1, const float* __restrict__ lW2,
    const float* __restrict__ sW0, const float* __restrict__ sW1, const float* __restrict__ sW2,
    const float* __restrict__ M0,  const float* __restrict__ M1,  const float* __restrict__ M2)
{
    int idx = blockIdx.x*blockDim.x + threadIdx.x;
    if (idx >= 32*WNET) return;
    int pair = idx / WNET, off = idx % WNET;
    int l = pair >> 1, net = pair & 1;
    float w; int n, k, wn, nl, itemoff, lodelta;
    if (off < W0_SZ){
        n = off >> 6; k = off & 63;
        int s = l*W0_SZ + off;
        w = (net ? sW0[s] : lW0[s]) * M0[s];
        wn = n >> 6; nl = n & 63;
        itemoff = (k >> 4)*4096; lodelta = 2048;
    } else if (off < W0_SZ + W1_SZ){
        int o = off - W0_SZ;
        n = o >> 8; k = o & 255;
        int s = l*W1_SZ + o;
        w = (net ? sW1[s] : lW1[s]) * M1[s];
        wn = n >> 6; nl = n & 63;
        itemoff = 16384 + (k >> 4)*4096; lodelta = 2048;
    } else {
        int o = off - W0_SZ - W1_SZ;
        n = o >> 8; k = o & 255;
        int s = l*W2_SZ + o;
        w = (net ? sW2[s] : lW2[s]) * M2[s];
        wn = n >> 4; nl = n & 15;
        itemoff = 81920 + (k >> 4)*1024; lodelta = 512;
    }
    int g = nl >> 4, nn = nl & 15, tt = nn >> 3, nrow = nn & 7, kl = k & 15;
    int T = (nrow << 2) | ((kl & 7) >> 1);
    int b = (tt << 1) | (kl >> 3);
    size_t dst = (size_t)wn*GRP_STRIDE + (size_t)pair*GRP_PAIR
               + itemoff + g*512 + T*16 + b*4 + ((kl & 1) << 1);
    __nv_bfloat16 hv = __float2bfloat16_rn(w);
    __nv_bfloat16 lv = __float2bfloat16_rn(w - __bfloat162float(hv));
    *(__nv_bfloat16*)(g_W + dst) = hv;
    *(__nv_bfloat16*)(g_W + dst + lodelta) = lv;
}

// ---------------- fused flow kernel ------------------------------------------
__global__ void __launch_bounds__(NTHREADS,2) flow_kernel(
    const float* __restrict__ u,
    const float* __restrict__ lb0, const float* __restrict__ lb1, const float* __restrict__ lb2,
    const float* __restrict__ sb0, const float* __restrict__ sb1, const float* __restrict__ sb2,
    float* __restrict__ out)
{
    extern __shared__ unsigned char smp[];
    u32 smb = s2u(smp);
    int tid = threadIdx.x, lane = tid & 31, wid = tid >> 5;
    int wm = wid >> 2, wn = wid & 3;
    int q = lane >> 3, ln = lane & 7;
    int row0 = blockIdx.x * TBR;
    float* loc_sm = (float*)(smp + SM_LOC);
    float* y_sm   = (float*)(smp + SM_Y);

    int r0  = wm*32 + (lane >> 2);
    int cb  = wn*64 + (lane & 3)*2;   // stage0/1 col base (N=256)
    int cb2 = wn*16 + (lane & 3)*2;   // stage2 col base (N=64)

    // per-thread weight stream base (fragment order: this lane's 16B slices)
    const unsigned char* tb = g_W + (size_t)wn*GRP_STRIDE + (size_t)lane*16;

    // init y smem + A tiles (cols 0..63)
    #pragma unroll
    for (int i = 0; i < 2; i++)
      #pragma unroll
      for (int j = 0; j < 2; j++)
        #pragma unroll
        for (int rr = 0; rr < 2; rr++){
          int row = r0 + i*16 + rr*8;
          int c = cb2 + j*8;
          float2 v = *(const float2*)(u + (size_t)(row0 + row)*DIM + c);
          *(float2*)&y_sm[row*66 + c] = v;
          writeA2(smp, row, c, v.x, v.y);
        }
    __syncthreads();

    float acc[16][4];
    uint4 bh[4];
    auto zacc = [&](){
        #pragma unroll
        for (int t = 0; t < 16; t++){ acc[t][0]=0.f; acc[t][1]=0.f; acc[t][2]=0.f; acc[t][3]=0.f; }
    };
    auto ldA = [&](u32 base, int kc, u32 (*r)[4]){
        u32 arow0 = (u32)(wm*32 + ((q & 1) << 3) + ln);
        u32 aunit = (u32)(kc*2 + (q >> 1));
        #pragma unroll
        for (int i = 0; i < 2; i++){
            u32 rr = arow0 + (u32)i*16u;
            u32 aoff = rr*512u + ((aunit ^ (rr & 7u)) << 4);
            ldsm4(r[i], base + aoff);
        }
    };
    // big chunk: bh preloaded; prefetches next item's hi between pass2 and pass3.
    // Per-acc accumulation order: ah*bh, al*bh, ah*bl (unchanged).
    auto big_chunk = [&](const unsigned char* wp_cur, int kc){
        uint4 bl[4];
        #pragma unroll
        for (int g = 0; g < 4; g++) bl[g] = *(const uint4*)(wp_cur + 2048 + g*512);
        u32 ah[2][4], al[2][4];
        ldA(smb + SM_AHI, kc, ah);
        ldA(smb + SM_ALO, kc, al);
        #pragma unroll
        for (int g = 0; g < 4; g++){
            const u32* bp = (const u32*)&bh[g];
            #pragma unroll
            for (int i = 0; i < 2; i++)
              #pragma unroll
              for (int tt = 0; tt < 2; tt++)
                mma_bf16(acc[i*8 + g*2 + tt], ah[i], bp + tt*2);
        }
        #pragma unroll
        for (int g = 0; g < 4; g++){
            const u32* bp = (const u32*)&bh[g];
            #pragma unroll
            for (int i = 0; i < 2; i++)
              #pragma unroll
              for (int tt = 0; tt < 2; tt++)
                mma_bf16(acc[i*8 + g*2 + tt], al[i], bp + tt*2);
        }
        #pragma unroll
        for (int g = 0; g < 4; g++) bh[g] = *(const uint4*)(wp_cur + 4096 + g*512);
        #pragma unroll
        for (int g = 0; g < 4; g++){
            const u32* bp = (const u32*)&bl[g];
            #pragma unroll
            for (int i = 0; i < 2; i++)
              #pragma unroll
              for (int tt = 0; tt < 2; tt++)
                mma_bf16(acc[i*8 + g*2 + tt], ah[i], bp + tt*2);
        }
    };
    // small chunk (stage2): bh[0] preloaded; prefetches next item's hi
    auto small_chunk = [&](const unsigned char* wp_cur, int kc){
        uint4 bl = *(const uint4*)(wp_cur + 512);
        u32 ah[2][4], al[2][4];
        ldA(smb + SM_AHI, kc, ah);
        ldA(smb + SM_ALO, kc, al);
        const u32* bhp = (const u32*)&bh[0];
        const u32* blp = (const u32*)&bl;
        #pragma unroll
        for (int i = 0; i < 2; i++)
          #pragma unroll
          for (int tt = 0; tt < 2; tt++)
            mma_bf16(acc[i*8 + tt], ah[i], bhp + tt*2);
        #pragma unroll
        for (int i = 0; i < 2; i++)
          #pragma unroll
          for (int tt = 0; tt < 2; tt++)
            mma_bf16(acc[i*8 + tt], al[i], bhp + tt*2);
        bh[0] = *(const uint4*)(wp_cur + 1024);
        #pragma unroll
        for (int i = 0; i < 2; i++)
          #pragma unroll
          for (int tt = 0; tt < 2; tt++)
            mma_bf16(acc[i*8 + tt], ah[i], blp + tt*2);
    };

    #pragma unroll 1
    for (int pair = 0; pair < 32; pair++){
        int l = pair >> 1, net = pair & 1;
        const float* b0 = (net ? sb0 : lb0) + l*NHID;
        const float* b1 = (net ? sb1 : lb1) + l*NHID;
        const float* b2 = (net ? sb2 : lb2) + l*DIM;
        const unsigned char* wp0 = tb + (size_t)pair*GRP_PAIR;

        // preload bh for stage0 chunk0
        #pragma unroll
        for (int g = 0; g < 4; g++) bh[g] = *(const uint4*)(wp0 + g*512);

        // ---- stage0: K=64 ----
        zacc();
        #pragma unroll 1
        for (int kc = 0; kc < 4; kc++) big_chunk(wp0 + kc*4096, kc);
        __syncthreads();
        #pragma unroll
        for (int i = 0; i < 2; i++)
          #pragma unroll
          for (int j = 0; j < 8; j++){
            int c = cb + j*8;
            float2 bb = *(const float2*)(b0 + c);
            float* d = acc[i*8 + j];
            writeA2(smp, r0 + i*16,     c, fmaxf(d[0]+bb.x,0.f), fmaxf(d[1]+bb.y,0.f));
            writeA2(smp, r0 + i*16 + 8, c, fmaxf(d[2]+bb.x,0.f), fmaxf(d[3]+bb.y,0.f));
          }
        __syncthreads();

        // ---- stage1: K=256 ---- (bh already prefetched by stage0's last chunk)
        zacc();
        #pragma unroll 1
        for (int kc = 0; kc < 16; kc++) big_chunk(wp0 + 16384 + kc*4096, kc);
        __syncthreads();
        #pragma unroll
        for (int i = 0; i < 2; i++)
          #pragma unroll
          for (int j = 0; j < 8; j++){
            int c = cb + j*8;
            float2 bb = *(const float2*)(b1 + c);
            float* d = acc[i*8 + j];
            writeA2(smp, r0 + i*16,     c, fmaxf(d[0]+bb.x,0.f), fmaxf(d[1]+bb.y,0.f));
            writeA2(smp, r0 + i*16 + 8, c, fmaxf(d[2]+bb.x,0.f), fmaxf(d[3]+bb.y,0.f));
          }
        __syncthreads();

        // ---- stage2: K=256, N=64 ----
        zacc();
        bh[0] = *(const uint4*)(wp0 + 81920);
        #pragma unroll 1
        for (int kc = 0; kc < 16; kc++) small_chunk(wp0 + 81920 + kc*1024, kc);
        __syncthreads();
        if (net == 0){
            #pragma unroll
            for (int i = 0; i < 2; i++)
              #pragma unroll
              for (int j = 0; j < 2; j++){
                int c = cb2 + j*8;
                float2 bb = *(const float2*)(b2 + c);
                float* d = acc[i*8 + j];
                int ra = r0 + i*16, rb = ra + 8;
                *(float2*)&loc_sm[ra*66 + c] = make_float2(d[0]+bb.x, d[1]+bb.y);
                *(float2*)&loc_sm[rb*66 + c] = make_float2(d[2]+bb.x, d[3]+bb.y);
                float2 ya = *(const float2*)&y_sm[ra*66 + c];
                float2 yb = *(const float2*)&y_sm[rb*66 + c];
                writeA2(smp, ra, c, ya.x, ya.y);
                writeA2(smp, rb, c, yb.x, yb.y);
              }
        } else {
            #pragma unroll
            for (int i = 0; i < 2; i++)
              #pragma unroll
              for (int j = 0; j < 2; j++){
                int c = cb2 + j*8;
                float2 bb = *(const float2*)(b2 + c);
                float* d = acc[i*8 + j];
                #pragma unroll
                for (int rr = 0; rr < 2; rr++){
                  int row = r0 + i*16 + rr*8;
                  float2 lc = *(const float2*)&loc_sm[row*66 + c];
                  float2 yo = *(const float2*)&y_sm[row*66 + c];
                  float y0 = expf(-(d[rr*2]  + bb.x)) * (yo.x - lc.x);
                  float y1 = expf(-(d[rr*2+1]+ bb.y)) * (yo.y - lc.y);
                  if (pair == 31){
                    *(float2*)(out + (size_t)(row0 + row)*DIM + c) = make_float2(y0, y1);
                  } else {
                    *(float2*)&y_sm[row*66 + c] = make_float2(y0, y1);
                    writeA2(smp, row, c, y0, y1);
                  }
                }
              }
        }
        __syncthreads();
    }
}

// ---------------- launch ------------------------------------------------------
extern "C" void kernel_launch(void* const* d_in, const int* in_sizes, int n_in,
                              void* d_out, int out_size)
{
    const float* u   = (const float*)d_in[0];
    const float* lW0 = (const float*)d_in[1];
    const float* lb0 = (const float*)d_in[2];
    const float* lW1 = (const float*)d_in[3];
    const float* lb1 = (const float*)d_in[4];
    const float* lW2 = (const float*)d_in[5];
    const float* lb2 = (const float*)d_in[6];
    const float* sW0 = (const float*)d_in[7];
    const float* sb0 = (const float*)d_in[8];
    const float* sW1 = (const float*)d_in[9];
    const float* sb1 = (const float*)d_in[10];
    const float* sW2 = (const float*)d_in[11];
    const float* sb2 = (const float*)d_in[12];
    const float* M0  = (const float*)d_in[13];
    const float* M1  = (const float*)d_in[14];
    const float* M2  = (const float*)d_in[15];

    int rows = in_sizes[0] / DIM;

    cudaFuncSetAttribute(flow_kernel, cudaFuncAttributeMaxDynamicSharedMemorySize, SM_TOTAL);

    const int total = 32*WNET;
    prep_kernel<<<(total + 255)/256, 256>>>(lW0, lW1, lW2, sW0, sW1, sW2, M0, M1, M2);

    flow_kernel<<<rows / TBR, NTHREADS, SM_TOTAL>>>(
        u, lb0, lb1, lb2, sb0, sb1, sb2, (float*)d_out);
}